// round 2
// baseline (speedup 1.0000x reference)
#include <cuda_runtime.h>
#include <math.h>

#define Nn 20000
#define Rr 400
#define Hh 200
#define Ee 200000
#define Tt 3
#define Bb 1024
#define Cc 50
#define CH (Cc*Hh)
#define SLOPEC 0.22916666666666666f
#define EPSN 1e-12f

// ---------------- scratch (device globals; no allocation allowed) ----------------
__device__ float g_ent[Nn*Hh];
__device__ float g_h1[Nn*Hh];
__device__ float g_h2[Nn*Hh];
__device__ float g_pre[Nn*Hh];
__device__ float g_S[Nn*Hh];
__device__ float g_U[Nn*Hh];
__device__ float g_winv[Nn];
__device__ float g_rnorm[Nn];
__device__ float g_relh[Rr*Hh];
__device__ float g_relent[Rr*Hh];
__device__ float g_x[Rr*2*Hh];
__device__ float g_gi[Rr*3*Hh];
__device__ float g_gh[Rr*3*Hh];
__device__ float g_nrel[Rr*Hh];
__device__ int   g_relCnt[Rr];
__device__ int   g_relBase[Rr+1];
__device__ int   g_relCur[Rr];
__device__ int   g_edgeByRel[Ee];
__device__ int   g_degCnt[Nn];
__device__ int   g_nodeBase[Nn+1];
__device__ int   g_nodeCur[Nn];
__device__ int   g_edgeByDst[Ee];
__device__ int   g_zeroList[Nn];
__device__ int   g_zeroCount;
__device__ float g_feat[Bb*CH];
__device__ float g_dec[Bb*Hh];
__device__ float g_e1[Bb*Hh];
__device__ float g_e2[Bb*Hh];

// ---------------- utility kernels ----------------

// out[r] = in[r] / max(||in[r]||, eps)   (one block per row)
__global__ void normalize_rows(const float* __restrict__ in, float* __restrict__ out, int rows) {
    int r = blockIdx.x;
    if (r >= rows) return;
    __shared__ float red[256];
    int t = threadIdx.x;
    float v = (t < Hh) ? in[r*Hh + t] : 0.f;
    red[t] = v*v;
    __syncthreads();
    for (int s = 128; s > 0; s >>= 1) { if (t < s) red[t] += red[t+s]; __syncthreads(); }
    float inv = 1.0f / fmaxf(sqrtf(red[0]), EPSN);
    if (t < Hh) out[r*Hh + t] = v * inv;
}

__global__ void zero_prep() {
    int i = blockIdx.x * blockDim.x + threadIdx.x;
    if (i < Nn) g_degCnt[i] = 0;
    if (i < Rr) g_relCnt[i] = 0;
    if (i == 0) g_zeroCount = 0;
}

__global__ void hist_kernel(const int* __restrict__ er, const int* __restrict__ ds) {
    int e = blockIdx.x * blockDim.x + threadIdx.x;
    if (e < Ee) {
        atomicAdd(&g_relCnt[er[e]], 1);
        atomicAdd(&g_degCnt[ds[e]], 1);
    }
}

__global__ void scan_rel() {
    if (threadIdx.x == 0) {
        int run = 0;
        for (int i = 0; i < Rr; i++) {
            int v = g_relCnt[i];
            g_relBase[i] = run; g_relCur[i] = run;
            run += v;
        }
        g_relBase[Rr] = run;
    }
}

__global__ void scan_node() {
    __shared__ int sm[1024];
    __shared__ int carry;
    int t = threadIdx.x;
    if (t == 0) carry = 0;
    __syncthreads();
    for (int base = 0; base < Nn; base += 1024) {
        int i = base + t;
        int v = (i < Nn) ? g_degCnt[i] : 0;
        sm[t] = v;
        __syncthreads();
        for (int off = 1; off < 1024; off <<= 1) {
            int y = (t >= off) ? sm[t - off] : 0;
            __syncthreads();
            sm[t] += y;
            __syncthreads();
        }
        int excl = sm[t] - v + carry;
        if (i < Nn) { g_nodeBase[i] = excl; g_nodeCur[i] = excl; }
        __syncthreads();
        if (t == 1023) carry += sm[1023];
        __syncthreads();
    }
    if (t == 0) g_nodeBase[Nn] = carry;
}

__global__ void scatter_edges(const int* __restrict__ er, const int* __restrict__ ds) {
    int e = blockIdx.x * blockDim.x + threadIdx.x;
    if (e < Ee) {
        int p1 = atomicAdd(&g_relCur[er[e]], 1);
        g_edgeByRel[p1] = e;
        int p2 = atomicAdd(&g_nodeCur[ds[e]], 1);
        g_edgeByDst[p2] = e;
    }
}

__global__ void build_misc() {
    int n = blockIdx.x * blockDim.x + threadIdx.x;
    if (n < Nn) {
        int d = g_degCnt[n];
        g_rnorm[n] = d > 0 ? 1.0f / (float)d : 0.0f;
        if (d == 0) {
            int i = atomicAdd(&g_zeroCount, 1);
            g_zeroList[i] = n;
        }
    }
}

// per-relation mean of ent[src[e]] over the sorted bucket  (no fp atomics)
__global__ void rel_mean(const int* __restrict__ srcT) {
    __shared__ int ss[256];
    int r = blockIdx.x, t = threadIdx.x;
    int b0 = g_relBase[r], b1 = g_relBase[r+1];
    float acc = 0.f;
    for (int cb = b0; cb < b1; cb += 256) {
        int m = min(256, b1 - cb);
        if (t < m) ss[t] = srcT[g_edgeByRel[cb + t]];
        __syncthreads();
        if (t < Hh) {
            int i = 0;
            for (; i + 3 < m; i += 4) {
                float a0 = g_ent[ss[i  ]*Hh + t];
                float a1 = g_ent[ss[i+1]*Hh + t];
                float a2 = g_ent[ss[i+2]*Hh + t];
                float a3 = g_ent[ss[i+3]*Hh + t];
                acc += a0 + a1 + a2 + a3;
            }
            for (; i < m; i++) acc += g_ent[ss[i]*Hh + t];
        }
        __syncthreads();
    }
    if (t < Hh) {
        int cnt = b1 - b0;
        g_relent[r*Hh + t] = cnt > 0 ? acc / (float)cnt : 0.f;
    }
}

__global__ void build_x(const float* __restrict__ rel_embeds) {
    int i = blockIdx.x * blockDim.x + threadIdx.x;
    if (i < Rr*2*Hh) {
        int r = i / (2*Hh), c = i % (2*Hh);
        g_x[i] = (c < Hh) ? rel_embeds[r*Hh + c] : g_relent[r*Hh + (c - Hh)];
    }
}

// GRU gates + l2norm of new hidden
__global__ void gru_gate() {
    int r = blockIdx.x, t = threadIdx.x;
    __shared__ float red[256];
    float hp = 0.f;
    if (t < Hh) {
        const float* gi = &g_gi[r*3*Hh];
        const float* gh = &g_gh[r*3*Hh];
        float h  = g_relh[r*Hh + t];
        float rr = 1.f / (1.f + expf(-(gi[t]        + gh[t])));
        float z  = 1.f / (1.f + expf(-(gi[Hh+t]     + gh[Hh+t])));
        float n  = tanhf(gi[2*Hh+t] + rr * gh[2*Hh+t]);
        hp = (1.f - z) * n + z * h;
    }
    red[t] = hp*hp;
    __syncthreads();
    for (int s = 128; s > 0; s >>= 1) { if (t < s) red[t] += red[t+s]; __syncthreads(); }
    float inv = 1.0f / fmaxf(sqrtf(red[0]), EPSN);
    if (t < Hh) g_nrel[r*Hh + t] = hp * inv;
}

// pre[n] = sum over edges into n of (h_in[src] + n_rel[erel])  (sorted, no atomics)
__global__ void gather_pre(const int* __restrict__ srcT, const int* __restrict__ erelT, int which) {
    const float* hin = which ? g_h1 : g_ent;
    __shared__ int ss[64];
    __shared__ int rs[64];
    int n = blockIdx.x, t = threadIdx.x;
    int b0 = g_nodeBase[n], b1 = g_nodeBase[n+1];
    float acc = 0.f;
    for (int cb = b0; cb < b1; cb += 64) {
        int m = min(64, b1 - cb);
        if (t < m) {
            int e = g_edgeByDst[cb + t];
            ss[t] = srcT[e];
            rs[t] = erelT[e];
        }
        __syncthreads();
        if (t < Hh) {
            for (int i = 0; i < m; i++)
                acc += hin[ss[i]*Hh + t] + g_nrel[rs[i]*Hh + t];
        }
        __syncthreads();
    }
    if (t < Hh) g_pre[n*Hh + t] = acc;
}

// deg==0 rows: out = rrelu(h_in @ Wel^T)
__global__ void fixup_zero(const float* __restrict__ Wel, int which) {
    const float* hin = which ? g_h1 : g_ent;
    float* out = which ? g_h2 : g_h1;
    __shared__ float hrow[Hh];
    for (int li = blockIdx.x; li < g_zeroCount; li += gridDim.x) {
        int n = g_zeroList[li];
        int t = threadIdx.x;
        if (t < Hh) hrow[t] = hin[n*Hh + t];
        __syncthreads();
        if (t < Hh) {
            float s = 0.f;
            for (int k = 0; k < Hh; k++) s += hrow[k] * Wel[t*Hh + k];
            out[n*Hh + t] = s >= 0.f ? s : SLOPEC * s;
        }
        __syncthreads();
    }
}

__global__ void rownorm_inv() {
    int row = blockIdx.x * 8 + (threadIdx.x >> 5);
    int lane = threadIdx.x & 31;
    if (row >= Nn) return;
    float s = 0.f;
    for (int c = lane; c < Hh; c += 32) { float v = g_h2[row*Hh + c]; s += v*v; }
    for (int o = 16; o > 0; o >>= 1) s += __shfl_xor_sync(0xffffffff, s, o);
    if (lane == 0) g_winv[row] = 1.0f / fmaxf(sqrtf(s), EPSN);
}

__global__ void update_ent() {
    int i = blockIdx.x * blockDim.x + threadIdx.x;
    if (i < Nn*Hh) {
        int row = i / Hh;
        float e = g_ent[i];
        float u = g_U[i];
        float w = g_h2[i] * g_winv[row];
        g_ent[i] = e + u * (w - e);
    }
}

__global__ void copy_relh() {
    int i = blockIdx.x * blockDim.x + threadIdx.x;
    if (i < Rr*Hh) g_relh[i] = g_nrel[i];
}

// ---------------- generic tiled GEMM: C = epi(A @ W^T) ----------------
// A: (M,K) row-major. W: (Nout,K) row-major. C: (M,Nout) row-major.
// EPI: 0 plain | 1 rrelu(rowscale[row]*acc + S) | 2 sigmoid(acc+bias) |
//      3 relu(acc+bias) | 4 acc+bias
template<int EPI>
__global__ void gemm_kernel(const float* __restrict__ A, const float* __restrict__ W,
                            float* __restrict__ C, int M, int Nout, int Kdim,
                            const float* __restrict__ bias,
                            const float* __restrict__ Sadd,
                            const float* __restrict__ rowscale) {
    __shared__ float As[16][64];
    __shared__ float Ws[16][64];
    int tx = threadIdx.x, ty = threadIdx.y;           // 16x16
    int tid = ty * 16 + tx;
    int j0 = blockIdx.x * 64;
    int i0 = blockIdx.y * 64;
    float acc[4][4];
#pragma unroll
    for (int a = 0; a < 4; a++)
#pragma unroll
        for (int b = 0; b < 4; b++) acc[a][b] = 0.f;

    for (int kt = 0; kt < Kdim; kt += 16) {
#pragma unroll
        for (int l = 0; l < 4; l++) {
            int idx = l * 256 + tid;
            int r = idx >> 4, k = idx & 15;
            int gr = i0 + r, gk = kt + k;
            As[k][r] = (gr < M && gk < Kdim) ? A[(size_t)gr * Kdim + gk] : 0.f;
            int wr = j0 + r;
            Ws[k][r] = (wr < Nout && gk < Kdim) ? W[(size_t)wr * Kdim + gk] : 0.f;
        }
        __syncthreads();
#pragma unroll
        for (int k = 0; k < 16; k++) {
            float4 a4 = *reinterpret_cast<const float4*>(&As[k][ty*4]);
            float4 w4 = *reinterpret_cast<const float4*>(&Ws[k][tx*4]);
            float av[4] = {a4.x, a4.y, a4.z, a4.w};
            float wv[4] = {w4.x, w4.y, w4.z, w4.w};
#pragma unroll
            for (int a = 0; a < 4; a++)
#pragma unroll
                for (int b = 0; b < 4; b++) acc[a][b] += av[a] * wv[b];
        }
        __syncthreads();
    }
#pragma unroll
    for (int a = 0; a < 4; a++) {
        int row = i0 + ty*4 + a;
        if (row >= M) continue;
#pragma unroll
        for (int b = 0; b < 4; b++) {
            int col = j0 + tx*4 + b;
            if (col >= Nout) continue;
            float v = acc[a][b];
            if (EPI == 1) {
                v = v * rowscale[row] + Sadd[(size_t)row * Nout + col];
                v = v >= 0.f ? v : SLOPEC * v;
            } else if (EPI == 2) {
                v += bias[col];
                v = 1.f / (1.f + expf(-v));
            } else if (EPI == 3) {
                v += bias[col];
                v = fmaxf(v, 0.f);
            } else if (EPI == 4) {
                v += bias[col];
            }
            C[(size_t)row * Nout + col] = v;
        }
    }
}

// ---------------- decoder ----------------

__global__ void dec_gather(const int* __restrict__ sidx, const int* __restrict__ oidx, int mode) {
    int i = blockIdx.x * blockDim.x + threadIdx.x;
    if (i < Bb*Hh) {
        int b = i / Hh, c = i % Hh;
        g_e1[i] = g_ent[sidx[b]*Hh + c];
        g_e2[i] = mode ? g_ent[oidx[b]*Hh + c] : g_relh[oidx[b]*Hh + c];
    }
}

__global__ void conv_feat(const float* __restrict__ cw, const float* __restrict__ cb) {
    int b = blockIdx.x;
    __shared__ float s1[Hh+2], s2[Hh+2];
    __shared__ float w[Cc*6];
    __shared__ float bb[Cc];
    int t = threadIdx.x;
    if (t < Hh) { s1[t+1] = g_e1[b*Hh + t]; s2[t+1] = g_e2[b*Hh + t]; }
    if (t == 0) { s1[0] = 0.f; s2[0] = 0.f; s1[Hh+1] = 0.f; s2[Hh+1] = 0.f; }
    for (int i = t; i < Cc*6; i += blockDim.x) w[i] = cw[i];
    if (t < Cc) bb[t] = cb[t];
    __syncthreads();
    for (int idx = t; idx < CH; idx += blockDim.x) {
        int c = idx / Hh, i = idx % Hh;
        const float* wc = &w[c*6];
        float v = bb[c]
            + s1[i]*wc[0] + s1[i+1]*wc[1] + s1[i+2]*wc[2]
            + s2[i]*wc[3] + s2[i+1]*wc[4] + s2[i+2]*wc[5];
        g_feat[(size_t)b*CH + idx] = fmaxf(v, 0.f);
    }
}

// ---------------- host ----------------

static void* symaddr(const void* s) { void* p = nullptr; cudaGetSymbolAddress(&p, s); return p; }

extern "C" void kernel_launch(void* const* d_in, const int* in_sizes, int n_in,
                              void* d_out, int out_size) {
    const float* ent_embeds = (const float*)d_in[0];
    const float* rel_embeds = (const float*)d_in[1];
    const float* Wr1  = (const float*)d_in[2];
    const float* Wsl1 = (const float*)d_in[3];
    const float* Wel1 = (const float*)d_in[4];
    const float* Wr2  = (const float*)d_in[5];
    const float* Wsl2 = (const float*)d_in[6];
    const float* Wel2 = (const float*)d_in[7];
    const float* lin_W = (const float*)d_in[8];
    const float* lin_b = (const float*)d_in[9];
    const float* gru_Wih = (const float*)d_in[10];
    const float* gru_Whh = (const float*)d_in[11];
    const float* gru_bih = (const float*)d_in[12];
    const float* gru_bhh = (const float*)d_in[13];
    const float* conve_w = (const float*)d_in[14];
    const float* conve_b = (const float*)d_in[15];
    const float* fce_w = (const float*)d_in[16];
    const float* fce_b = (const float*)d_in[17];
    const float* convr_w = (const float*)d_in[18];
    const float* convr_b = (const float*)d_in[19];
    const float* fcr_w = (const float*)d_in[20];
    const float* fcr_b = (const float*)d_in[21];
    const int* src  = (const int*)d_in[22];
    const int* dst  = (const int*)d_in[23];
    const int* erel = (const int*)d_in[24];
    const int* subj = (const int*)d_in[25];
    const int* relI = (const int*)d_in[26];
    const int* objI = (const int*)d_in[27];
    float* out = (float*)d_out;

    float* p_ent   = (float*)symaddr(g_ent);
    float* p_h1    = (float*)symaddr(g_h1);
    float* p_h2    = (float*)symaddr(g_h2);
    float* p_pre   = (float*)symaddr(g_pre);
    float* p_S     = (float*)symaddr(g_S);
    float* p_U     = (float*)symaddr(g_U);
    float* p_rnorm = (float*)symaddr(g_rnorm);
    float* p_relh  = (float*)symaddr(g_relh);
    float* p_x     = (float*)symaddr(g_x);
    float* p_gi    = (float*)symaddr(g_gi);
    float* p_gh    = (float*)symaddr(g_gh);
    float* p_feat  = (float*)symaddr(g_feat);
    float* p_dec   = (float*)symaddr(g_dec);

    dim3 t16(16, 16);

    // init: l2 normalize embeddings
    normalize_rows<<<Nn, 256>>>(ent_embeds, p_ent, Nn);
    normalize_rows<<<Rr, 256>>>(rel_embeds, p_relh, Rr);

    const float* Wr_[2]  = {Wr1, Wr2};
    const float* Wsl_[2] = {Wsl1, Wsl2};
    const float* Wel_[2] = {Wel1, Wel2};

    for (int t = 0; t < Tt; t++) {
        const int* srcT  = src  + t*Ee;
        const int* dstT  = dst  + t*Ee;
        const int* erelT = erel + t*Ee;

        zero_prep<<<(Nn + 255)/256, 256>>>();
        hist_kernel<<<(Ee + 255)/256, 256>>>(erelT, dstT);
        scan_rel<<<1, 32>>>();
        scan_node<<<1, 1024>>>();
        scatter_edges<<<(Ee + 255)/256, 256>>>(erelT, dstT);
        build_misc<<<(Nn + 255)/256, 256>>>();

        // relation-level GRU
        rel_mean<<<Rr, 256>>>(srcT);
        build_x<<<(Rr*2*Hh + 255)/256, 256>>>(rel_embeds);
        gemm_kernel<4><<<dim3((3*Hh+63)/64, (Rr+63)/64), t16>>>(p_x, gru_Wih, p_gi, Rr, 3*Hh, 2*Hh, gru_bih, nullptr, nullptr);
        gemm_kernel<4><<<dim3((3*Hh+63)/64, (Rr+63)/64), t16>>>(p_relh, gru_Whh, p_gh, Rr, 3*Hh, Hh, gru_bhh, nullptr, nullptr);
        gru_gate<<<Rr, 256>>>();

        // two RGCN layers (scatter-then-GEMM factorization)
        for (int l = 0; l < 2; l++) {
            const float* hin = (l == 0) ? p_ent : p_h1;
            float* hout = (l == 0) ? p_h1 : p_h2;
            gather_pre<<<Nn, 256>>>(srcT, erelT, l);
            gemm_kernel<0><<<dim3((Hh+63)/64, (Nn+63)/64), t16>>>(hin, Wsl_[l], p_S, Nn, Hh, Hh, nullptr, nullptr, nullptr);
            gemm_kernel<1><<<dim3((Hh+63)/64, (Nn+63)/64), t16>>>(p_pre, Wr_[l], hout, Nn, Hh, Hh, nullptr, p_S, p_rnorm);
            fixup_zero<<<64, 256>>>(Wel_[l], l);
        }

        // entity update
        rownorm_inv<<<(Nn + 7)/8, 256>>>();
        gemm_kernel<2><<<dim3((Hh+63)/64, (Nn+63)/64), t16>>>(p_ent, lin_W, p_U, Nn, Hh, Hh, lin_b, nullptr, nullptr);
        update_ent<<<(Nn*Hh + 255)/256, 256>>>();
        copy_relh<<<(Rr*Hh + 255)/256, 256>>>();
    }

    // ---- decoder: obj logits ----
    dec_gather<<<(Bb*Hh + 255)/256, 256>>>(subj, relI, 0);
    conv_feat<<<Bb, 256>>>(conve_w, conve_b);
    gemm_kernel<3><<<dim3((Hh+63)/64, (Bb+63)/64), t16>>>(p_feat, fce_w, p_dec, Bb, Hh, CH, fce_b, nullptr, nullptr);
    gemm_kernel<0><<<dim3((Nn+63)/64, (Bb+63)/64), t16>>>(p_dec, p_ent, out, Bb, Nn, Hh, nullptr, nullptr, nullptr);

    // ---- decoder: rel logits ----
    dec_gather<<<(Bb*Hh + 255)/256, 256>>>(subj, objI, 1);
    conv_feat<<<Bb, 256>>>(convr_w, convr_b);
    gemm_kernel<3><<<dim3((Hh+63)/64, (Bb+63)/64), t16>>>(p_feat, fcr_w, p_dec, Bb, Hh, CH, fcr_b, nullptr, nullptr);
    gemm_kernel<0><<<dim3((Rr+63)/64, (Bb+63)/64), t16>>>(p_dec, p_relh, out + (size_t)Bb*Nn, Bb, Rr, Hh, nullptr, nullptr, nullptr);
}

// round 3
// speedup vs baseline: 1.7727x; 1.7727x over previous
#include <cuda_runtime.h>
#include <math.h>

#define Nn 20000
#define Rr 400
#define Hh 200
#define Ee 200000
#define Tt 3
#define Bb 1024
#define Cc 50
#define CH (Cc*Hh)
#define KSPLIT 10
#define SLOPEC 0.22916666666666666f
#define EPSN 1e-12f

// ---------------- scratch (device globals; no allocation allowed) ----------------
__device__ float g_ent[Nn*Hh];
__device__ float g_h1[Nn*Hh];
__device__ float g_h2[Nn*Hh];
__device__ float g_pre[Nn*Hh];
__device__ float g_S[Nn*Hh];
__device__ float g_U[Nn*Hh];
__device__ float g_winv[Nn];
__device__ float g_rnorm[Nn];
__device__ float g_relh[Rr*Hh];
__device__ float g_relent[Rr*Hh];
__device__ float g_x[Rr*2*Hh];
__device__ float g_gi[Rr*3*Hh];
__device__ float g_gh[Rr*3*Hh];
__device__ float g_nrel[Rr*Hh];
__device__ int   g_relCnt[Rr];
__device__ int   g_relBase[Rr+1];
__device__ int   g_relCur[Rr];
__device__ int   g_edgeByRel[Ee];
__device__ int   g_degCnt[Nn];
__device__ int   g_nodeBase[Nn+1];
__device__ int   g_nodeCur[Nn];
__device__ int   g_edgeByDst[Ee];
__device__ int   g_zeroList[Nn];
__device__ int   g_zeroCount;
__device__ float g_feat[Bb*CH];
__device__ float g_dec[Bb*Hh];
__device__ float g_e1[Bb*Hh];
__device__ float g_e2[Bb*Hh];
__device__ float g_part[KSPLIT*Bb*Hh];

// ---------------- utility kernels ----------------

__global__ void normalize_rows(const float* __restrict__ in, float* __restrict__ out, int rows) {
    int r = blockIdx.x;
    if (r >= rows) return;
    __shared__ float red[256];
    int t = threadIdx.x;
    float v = (t < Hh) ? in[r*Hh + t] : 0.f;
    red[t] = v*v;
    __syncthreads();
    for (int s = 128; s > 0; s >>= 1) { if (t < s) red[t] += red[t+s]; __syncthreads(); }
    float inv = 1.0f / fmaxf(sqrtf(red[0]), EPSN);
    if (t < Hh) out[r*Hh + t] = v * inv;
}

__global__ void zero_prep() {
    int i = blockIdx.x * blockDim.x + threadIdx.x;
    if (i < Nn) g_degCnt[i] = 0;
    if (i < Rr) g_relCnt[i] = 0;
    if (i == 0) g_zeroCount = 0;
}

__global__ void hist_kernel(const int* __restrict__ er, const int* __restrict__ ds) {
    int e = blockIdx.x * blockDim.x + threadIdx.x;
    if (e < Ee) {
        atomicAdd(&g_relCnt[er[e]], 1);
        atomicAdd(&g_degCnt[ds[e]], 1);
    }
}

__global__ void scan_rel() {
    if (threadIdx.x == 0) {
        int run = 0;
        for (int i = 0; i < Rr; i++) {
            int v = g_relCnt[i];
            g_relBase[i] = run; g_relCur[i] = run;
            run += v;
        }
        g_relBase[Rr] = run;
    }
}

__global__ void scan_node() {
    __shared__ int sm[1024];
    __shared__ int carry;
    int t = threadIdx.x;
    if (t == 0) carry = 0;
    __syncthreads();
    for (int base = 0; base < Nn; base += 1024) {
        int i = base + t;
        int v = (i < Nn) ? g_degCnt[i] : 0;
        sm[t] = v;
        __syncthreads();
        for (int off = 1; off < 1024; off <<= 1) {
            int y = (t >= off) ? sm[t - off] : 0;
            __syncthreads();
            sm[t] += y;
            __syncthreads();
        }
        int excl = sm[t] - v + carry;
        if (i < Nn) { g_nodeBase[i] = excl; g_nodeCur[i] = excl; }
        __syncthreads();
        if (t == 1023) carry += sm[1023];
        __syncthreads();
    }
    if (t == 0) g_nodeBase[Nn] = carry;
}

__global__ void scatter_edges(const int* __restrict__ er, const int* __restrict__ ds) {
    int e = blockIdx.x * blockDim.x + threadIdx.x;
    if (e < Ee) {
        int p1 = atomicAdd(&g_relCur[er[e]], 1);
        g_edgeByRel[p1] = e;
        int p2 = atomicAdd(&g_nodeCur[ds[e]], 1);
        g_edgeByDst[p2] = e;
    }
}

__global__ void build_misc() {
    int n = blockIdx.x * blockDim.x + threadIdx.x;
    if (n < Nn) {
        int d = g_degCnt[n];
        g_rnorm[n] = d > 0 ? 1.0f / (float)d : 0.0f;
        if (d == 0) {
            int i = atomicAdd(&g_zeroCount, 1);
            g_zeroList[i] = n;
        }
    }
}

__global__ void rel_mean(const int* __restrict__ srcT) {
    __shared__ int ss[256];
    int r = blockIdx.x, t = threadIdx.x;
    int b0 = g_relBase[r], b1 = g_relBase[r+1];
    float acc = 0.f;
    for (int cb = b0; cb < b1; cb += 256) {
        int m = min(256, b1 - cb);
        if (t < m) ss[t] = srcT[g_edgeByRel[cb + t]];
        __syncthreads();
        if (t < Hh) {
            int i = 0;
            for (; i + 3 < m; i += 4) {
                float a0 = g_ent[ss[i  ]*Hh + t];
                float a1 = g_ent[ss[i+1]*Hh + t];
                float a2 = g_ent[ss[i+2]*Hh + t];
                float a3 = g_ent[ss[i+3]*Hh + t];
                acc += a0 + a1 + a2 + a3;
            }
            for (; i < m; i++) acc += g_ent[ss[i]*Hh + t];
        }
        __syncthreads();
    }
    if (t < Hh) {
        int cnt = b1 - b0;
        g_relent[r*Hh + t] = cnt > 0 ? acc / (float)cnt : 0.f;
    }
}

__global__ void build_x(const float* __restrict__ rel_embeds) {
    int i = blockIdx.x * blockDim.x + threadIdx.x;
    if (i < Rr*2*Hh) {
        int r = i / (2*Hh), c = i % (2*Hh);
        g_x[i] = (c < Hh) ? rel_embeds[r*Hh + c] : g_relent[r*Hh + (c - Hh)];
    }
}

__global__ void gru_gate() {
    int r = blockIdx.x, t = threadIdx.x;
    __shared__ float red[256];
    float hp = 0.f;
    if (t < Hh) {
        const float* gi = &g_gi[r*3*Hh];
        const float* gh = &g_gh[r*3*Hh];
        float h  = g_relh[r*Hh + t];
        float rr = 1.f / (1.f + expf(-(gi[t]        + gh[t])));
        float z  = 1.f / (1.f + expf(-(gi[Hh+t]     + gh[Hh+t])));
        float n  = tanhf(gi[2*Hh+t] + rr * gh[2*Hh+t]);
        hp = (1.f - z) * n + z * h;
    }
    red[t] = hp*hp;
    __syncthreads();
    for (int s = 128; s > 0; s >>= 1) { if (t < s) red[t] += red[t+s]; __syncthreads(); }
    float inv = 1.0f / fmaxf(sqrtf(red[0]), EPSN);
    if (t < Hh) g_nrel[r*Hh + t] = hp * inv;
}

__global__ void gather_pre(const int* __restrict__ srcT, const int* __restrict__ erelT, int which) {
    const float* hin = which ? g_h1 : g_ent;
    __shared__ int ss[64];
    __shared__ int rs[64];
    int n = blockIdx.x, t = threadIdx.x;
    int b0 = g_nodeBase[n], b1 = g_nodeBase[n+1];
    float acc = 0.f;
    for (int cb = b0; cb < b1; cb += 64) {
        int m = min(64, b1 - cb);
        if (t < m) {
            int e = g_edgeByDst[cb + t];
            ss[t] = srcT[e];
            rs[t] = erelT[e];
        }
        __syncthreads();
        if (t < Hh) {
            for (int i = 0; i < m; i++)
                acc += hin[ss[i]*Hh + t] + g_nrel[rs[i]*Hh + t];
        }
        __syncthreads();
    }
    if (t < Hh) g_pre[n*Hh + t] = acc;
}

__global__ void fixup_zero(const float* __restrict__ Wel, int which) {
    const float* hin = which ? g_h1 : g_ent;
    float* out = which ? g_h2 : g_h1;
    __shared__ float hrow[Hh];
    for (int li = blockIdx.x; li < g_zeroCount; li += gridDim.x) {
        int n = g_zeroList[li];
        int t = threadIdx.x;
        if (t < Hh) hrow[t] = hin[n*Hh + t];
        __syncthreads();
        if (t < Hh) {
            float s = 0.f;
            for (int k = 0; k < Hh; k++) s += hrow[k] * Wel[t*Hh + k];
            out[n*Hh + t] = s >= 0.f ? s : SLOPEC * s;
        }
        __syncthreads();
    }
}

__global__ void rownorm_inv() {
    int row = blockIdx.x * 8 + (threadIdx.x >> 5);
    int lane = threadIdx.x & 31;
    if (row >= Nn) return;
    float s = 0.f;
    for (int c = lane; c < Hh; c += 32) { float v = g_h2[row*Hh + c]; s += v*v; }
    for (int o = 16; o > 0; o >>= 1) s += __shfl_xor_sync(0xffffffff, s, o);
    if (lane == 0) g_winv[row] = 1.0f / fmaxf(sqrtf(s), EPSN);
}

__global__ void update_ent() {
    int i = blockIdx.x * blockDim.x + threadIdx.x;
    if (i < Nn*Hh) {
        int row = i / Hh;
        float e = g_ent[i];
        float u = g_U[i];
        float w = g_h2[i] * g_winv[row];
        g_ent[i] = e + u * (w - e);
    }
}

__global__ void copy_relh() {
    int i = blockIdx.x * blockDim.x + threadIdx.x;
    if (i < Rr*Hh) g_relh[i] = g_nrel[i];
}

// ---------------- tiled GEMM: C = epi(A @ W^T) ----------------
// A: (M,K) row-major. W: (Nout,K) row-major. C: (M,Nout) row-major.
// Block tile 128x64, 256 threads, per-thread fragment 8x4, BK=16.
// EPI: 0 plain | 1 rrelu(rowscale[row]*acc + S) | 2 sigmoid(acc+bias) |
//      3 relu(acc+bias) | 4 acc+bias
// SPLIT>1: grid.z splits K into chunks of klen; raw partials written to
//          C[z*M*Nout + ...] (EPI must be 0-style raw).
template<int EPI, int SPLIT>
__global__ void __launch_bounds__(256)
gemm128(const float* __restrict__ A, const float* __restrict__ W,
        float* __restrict__ C, int M, int Nout, int Kdim, int klen,
        const float* __restrict__ bias,
        const float* __restrict__ Sadd,
        const float* __restrict__ rowscale) {
    __shared__ float As[16][128];
    __shared__ float Ws[16][64];
    int tid = threadIdx.x;
    int tx = tid & 15, ty = tid >> 4;
    int j0 = blockIdx.x * 64;
    int i0 = blockIdx.y * 128;
    int k0 = (SPLIT > 1) ? blockIdx.z * klen : 0;
    int k1 = (SPLIT > 1) ? min(Kdim, k0 + klen) : Kdim;

    float acc[8][4];
#pragma unroll
    for (int a = 0; a < 8; a++)
#pragma unroll
        for (int b = 0; b < 4; b++) acc[a][b] = 0.f;

    int arow = tid >> 1;            // 0..127
    int akoff = (tid & 1) * 8;
    int wrow = tid >> 2;            // 0..63
    int wkoff = (tid & 3) * 4;
    int gr = i0 + arow;
    int wr = j0 + wrow;
    bool rok = gr < M;
    bool wok = wr < Nout;
    const float* Arow = A + (size_t)gr * Kdim;
    const float* Wrow = W + (size_t)wr * Kdim;

    for (int kt = k0; kt < k1; kt += 16) {
        int gka = kt + akoff;
        if (rok && gka + 7 < k1) {
            float4 v0 = *reinterpret_cast<const float4*>(Arow + gka);
            float4 v1 = *reinterpret_cast<const float4*>(Arow + gka + 4);
            As[akoff+0][arow] = v0.x; As[akoff+1][arow] = v0.y;
            As[akoff+2][arow] = v0.z; As[akoff+3][arow] = v0.w;
            As[akoff+4][arow] = v1.x; As[akoff+5][arow] = v1.y;
            As[akoff+6][arow] = v1.z; As[akoff+7][arow] = v1.w;
        } else {
#pragma unroll
            for (int q = 0; q < 8; q++)
                As[akoff+q][arow] = (rok && gka + q < k1) ? Arow[gka + q] : 0.f;
        }
        int gkw = kt + wkoff;
        if (wok && gkw + 3 < k1) {
            float4 v = *reinterpret_cast<const float4*>(Wrow + gkw);
            Ws[wkoff+0][wrow] = v.x; Ws[wkoff+1][wrow] = v.y;
            Ws[wkoff+2][wrow] = v.z; Ws[wkoff+3][wrow] = v.w;
        } else {
#pragma unroll
            for (int q = 0; q < 4; q++)
                Ws[wkoff+q][wrow] = (wok && gkw + q < k1) ? Wrow[gkw + q] : 0.f;
        }
        __syncthreads();
#pragma unroll
        for (int k = 0; k < 16; k++) {
            float4 a0 = *reinterpret_cast<const float4*>(&As[k][ty*8]);
            float4 a1 = *reinterpret_cast<const float4*>(&As[k][ty*8 + 4]);
            float4 w0 = *reinterpret_cast<const float4*>(&Ws[k][tx*4]);
            float av[8] = {a0.x, a0.y, a0.z, a0.w, a1.x, a1.y, a1.z, a1.w};
            float wv[4] = {w0.x, w0.y, w0.z, w0.w};
#pragma unroll
            for (int a = 0; a < 8; a++)
#pragma unroll
                for (int b = 0; b < 4; b++) acc[a][b] += av[a] * wv[b];
        }
        __syncthreads();
    }

    float* Cb = (SPLIT > 1) ? C + (size_t)blockIdx.z * M * Nout : C;
#pragma unroll
    for (int a = 0; a < 8; a++) {
        int row = i0 + ty*8 + a;
        if (row >= M) continue;
#pragma unroll
        for (int b = 0; b < 4; b++) {
            int col = j0 + tx*4 + b;
            if (col >= Nout) continue;
            float v = acc[a][b];
            if (EPI == 1) {
                v = v * rowscale[row] + Sadd[(size_t)row * Nout + col];
                v = v >= 0.f ? v : SLOPEC * v;
            } else if (EPI == 2) {
                v += bias[col];
                v = 1.f / (1.f + expf(-v));
            } else if (EPI == 3) {
                v += bias[col];
                v = fmaxf(v, 0.f);
            } else if (EPI == 4) {
                v += bias[col];
            }
            Cb[(size_t)row * Nout + col] = v;
        }
    }
}

// deterministic split-K reduction + bias + relu  (fc decoder output)
__global__ void split_reduce_relu(float* __restrict__ dst, const float* __restrict__ bias) {
    int i = blockIdx.x * blockDim.x + threadIdx.x;
    if (i < Bb*Hh) {
        float s = 0.f;
#pragma unroll
        for (int z = 0; z < KSPLIT; z++) s += g_part[(size_t)z * Bb * Hh + i];
        s += bias[i % Hh];
        dst[i] = fmaxf(s, 0.f);
    }
}

// ---------------- decoder ----------------

__global__ void dec_gather(const int* __restrict__ sidx, const int* __restrict__ oidx, int mode) {
    int i = blockIdx.x * blockDim.x + threadIdx.x;
    if (i < Bb*Hh) {
        int b = i / Hh, c = i % Hh;
        g_e1[i] = g_ent[sidx[b]*Hh + c];
        g_e2[i] = mode ? g_ent[oidx[b]*Hh + c] : g_relh[oidx[b]*Hh + c];
    }
}

__global__ void conv_feat(const float* __restrict__ cw, const float* __restrict__ cb) {
    int b = blockIdx.x;
    __shared__ float s1[Hh+2], s2[Hh+2];
    __shared__ float w[Cc*6];
    __shared__ float bb[Cc];
    int t = threadIdx.x;
    if (t < Hh) { s1[t+1] = g_e1[b*Hh + t]; s2[t+1] = g_e2[b*Hh + t]; }
    if (t == 0) { s1[0] = 0.f; s2[0] = 0.f; s1[Hh+1] = 0.f; s2[Hh+1] = 0.f; }
    for (int i = t; i < Cc*6; i += blockDim.x) w[i] = cw[i];
    if (t < Cc) bb[t] = cb[t];
    __syncthreads();
    for (int idx = t; idx < CH; idx += blockDim.x) {
        int c = idx / Hh, i = idx % Hh;
        const float* wc = &w[c*6];
        float v = bb[c]
            + s1[i]*wc[0] + s1[i+1]*wc[1] + s1[i+2]*wc[2]
            + s2[i]*wc[3] + s2[i+1]*wc[4] + s2[i+2]*wc[5];
        g_feat[(size_t)b*CH + idx] = fmaxf(v, 0.f);
    }
}

// ---------------- host ----------------

static void* symaddr(const void* s) { void* p = nullptr; cudaGetSymbolAddress(&p, s); return p; }

extern "C" void kernel_launch(void* const* d_in, const int* in_sizes, int n_in,
                              void* d_out, int out_size) {
    const float* ent_embeds = (const float*)d_in[0];
    const float* rel_embeds = (const float*)d_in[1];
    const float* Wr1  = (const float*)d_in[2];
    const float* Wsl1 = (const float*)d_in[3];
    const float* Wel1 = (const float*)d_in[4];
    const float* Wr2  = (const float*)d_in[5];
    const float* Wsl2 = (const float*)d_in[6];
    const float* Wel2 = (const float*)d_in[7];
    const float* lin_W = (const float*)d_in[8];
    const float* lin_b = (const float*)d_in[9];
    const float* gru_Wih = (const float*)d_in[10];
    const float* gru_Whh = (const float*)d_in[11];
    const float* gru_bih = (const float*)d_in[12];
    const float* gru_bhh = (const float*)d_in[13];
    const float* conve_w = (const float*)d_in[14];
    const float* conve_b = (const float*)d_in[15];
    const float* fce_w = (const float*)d_in[16];
    const float* fce_b = (const float*)d_in[17];
    const float* convr_w = (const float*)d_in[18];
    const float* convr_b = (const float*)d_in[19];
    const float* fcr_w = (const float*)d_in[20];
    const float* fcr_b = (const float*)d_in[21];
    const int* src  = (const int*)d_in[22];
    const int* dst  = (const int*)d_in[23];
    const int* erel = (const int*)d_in[24];
    const int* subj = (const int*)d_in[25];
    const int* relI = (const int*)d_in[26];
    const int* objI = (const int*)d_in[27];
    float* out = (float*)d_out;

    float* p_ent   = (float*)symaddr(g_ent);
    float* p_h1    = (float*)symaddr(g_h1);
    float* p_h2    = (float*)symaddr(g_h2);
    float* p_pre   = (float*)symaddr(g_pre);
    float* p_S     = (float*)symaddr(g_S);
    float* p_U     = (float*)symaddr(g_U);
    float* p_rnorm = (float*)symaddr(g_rnorm);
    float* p_relh  = (float*)symaddr(g_relh);
    float* p_x     = (float*)symaddr(g_x);
    float* p_gi    = (float*)symaddr(g_gi);
    float* p_gh    = (float*)symaddr(g_gh);
    float* p_feat  = (float*)symaddr(g_feat);
    float* p_dec   = (float*)symaddr(g_dec);
    float* p_part  = (float*)symaddr(g_part);

    normalize_rows<<<Nn, 256>>>(ent_embeds, p_ent, Nn);
    normalize_rows<<<Rr, 256>>>(rel_embeds, p_relh, Rr);

    const float* Wr_[2]  = {Wr1, Wr2};
    const float* Wsl_[2] = {Wsl1, Wsl2};
    const float* Wel_[2] = {Wel1, Wel2};

    #define GX(Nc) (((Nc)+63)/64)
    #define GY(Mr) (((Mr)+127)/128)

    for (int t = 0; t < Tt; t++) {
        const int* srcT  = src  + t*Ee;
        const int* dstT  = dst  + t*Ee;
        const int* erelT = erel + t*Ee;

        zero_prep<<<(Nn + 255)/256, 256>>>();
        hist_kernel<<<(Ee + 255)/256, 256>>>(erelT, dstT);
        scan_rel<<<1, 32>>>();
        scan_node<<<1, 1024>>>();
        scatter_edges<<<(Ee + 255)/256, 256>>>(erelT, dstT);
        build_misc<<<(Nn + 255)/256, 256>>>();

        // relation-level GRU
        rel_mean<<<Rr, 256>>>(srcT);
        build_x<<<(Rr*2*Hh + 255)/256, 256>>>(rel_embeds);
        gemm128<4,1><<<dim3(GX(3*Hh), GY(Rr)), 256>>>(p_x, gru_Wih, p_gi, Rr, 3*Hh, 2*Hh, 0, gru_bih, nullptr, nullptr);
        gemm128<4,1><<<dim3(GX(3*Hh), GY(Rr)), 256>>>(p_relh, gru_Whh, p_gh, Rr, 3*Hh, Hh, 0, gru_bhh, nullptr, nullptr);
        gru_gate<<<Rr, 256>>>();

        // two RGCN layers (scatter-then-GEMM factorization)
        for (int l = 0; l < 2; l++) {
            const float* hin = (l == 0) ? p_ent : p_h1;
            float* hout = (l == 0) ? p_h1 : p_h2;
            gather_pre<<<Nn, 256>>>(srcT, erelT, l);
            gemm128<0,1><<<dim3(GX(Hh), GY(Nn)), 256>>>(hin, Wsl_[l], p_S, Nn, Hh, Hh, 0, nullptr, nullptr, nullptr);
            gemm128<1,1><<<dim3(GX(Hh), GY(Nn)), 256>>>(p_pre, Wr_[l], hout, Nn, Hh, Hh, 0, nullptr, p_S, p_rnorm);
            fixup_zero<<<64, 256>>>(Wel_[l], l);
        }

        // entity update
        rownorm_inv<<<(Nn + 7)/8, 256>>>();
        gemm128<2,1><<<dim3(GX(Hh), GY(Nn)), 256>>>(p_ent, lin_W, p_U, Nn, Hh, Hh, 0, lin_b, nullptr, nullptr);
        update_ent<<<(Nn*Hh + 255)/256, 256>>>();
        copy_relh<<<(Rr*Hh + 255)/256, 256>>>();
    }

    const int klen = CH / KSPLIT;   // 1000

    // ---- decoder: obj logits ----
    dec_gather<<<(Bb*Hh + 255)/256, 256>>>(subj, relI, 0);
    conv_feat<<<Bb, 256>>>(conve_w, conve_b);
    gemm128<0,KSPLIT><<<dim3(GX(Hh), GY(Bb), KSPLIT), 256>>>(p_feat, fce_w, p_part, Bb, Hh, CH, klen, nullptr, nullptr, nullptr);
    split_reduce_relu<<<(Bb*Hh + 255)/256, 256>>>(p_dec, fce_b);
    gemm128<0,1><<<dim3(GX(Nn), GY(Bb)), 256>>>(p_dec, p_ent, out, Bb, Nn, Hh, 0, nullptr, nullptr, nullptr);

    // ---- decoder: rel logits ----
    dec_gather<<<(Bb*Hh + 255)/256, 256>>>(subj, objI, 1);
    conv_feat<<<Bb, 256>>>(convr_w, convr_b);
    gemm128<0,KSPLIT><<<dim3(GX(Hh), GY(Bb), KSPLIT), 256>>>(p_feat, fcr_w, p_part, Bb, Hh, CH, klen, nullptr, nullptr, nullptr);
    split_reduce_relu<<<(Bb*Hh + 255)/256, 256>>>(p_dec, fcr_b);
    gemm128<0,1><<<dim3(GX(Rr), GY(Bb)), 256>>>(p_dec, p_relh, out + (size_t)Bb*Nn, Bb, Rr, Hh, 0, nullptr, nullptr, nullptr);
}

// round 4
// speedup vs baseline: 2.4536x; 1.3841x over previous
#include <cuda_runtime.h>
#include <math.h>
#include <stdint.h>

#define Nn 20000
#define Rr 400
#define Hh 200
#define Ee 200000
#define Tt 3
#define Bb 1024
#define Cc 50
#define CH (Cc*Hh)
#define KSPLIT 10
#define NBLK ((Nn + 255) / 256)
#define SLOPEC 0.22916666666666666f
#define EPSN 1e-12f

// ---------------- scratch (device globals; no allocation allowed) ----------------
__device__ float g_ent[Nn*Hh];
__device__ float g_entB[Nn*Hh];
__device__ float g_h1[Nn*Hh];
__device__ float g_h2[Nn*Hh];
__device__ float g_pre[Nn*Hh];
__device__ float g_S[Nn*Hh];
__device__ float g_winv[Nn];
__device__ float g_rnorm[Nn];
__device__ float g_relh[Rr*Hh];
__device__ float g_relent[Rr*Hh];
__device__ float g_x[Rr*2*Hh];
__device__ float g_gi[Rr*3*Hh];
__device__ float g_gh[Rr*3*Hh];
__device__ float g_nrel[Rr*Hh];
__device__ int   g_relCnt[Rr];
__device__ int   g_relBase[Rr+1];
__device__ int   g_relCur[Rr];
__device__ int   g_edgeByRel[Ee];
__device__ int   g_degCnt[Nn];
__device__ int   g_nodeBase[Nn+1];
__device__ int   g_nodeCur[Nn];
__device__ int   g_edgeByDst[Ee];
__device__ int   g_blkSum[NBLK];
__device__ int   g_blkOff[NBLK];
__device__ int   g_zeroList[Nn];
__device__ int   g_zeroCount;
__device__ float g_feat[Bb*CH];
__device__ float g_dec[Bb*Hh];
__device__ float g_e1[Bb*Hh];
__device__ float g_e2[Bb*Hh];
__device__ float g_part[KSPLIT*Bb*Hh];

// ---------------- tf32 helpers ----------------
__device__ __forceinline__ float to_tf32(float x) {
    uint32_t u;
    asm("cvt.rna.tf32.f32 %0, %1;" : "=r"(u) : "r"(__float_as_uint(x)));
    return __uint_as_float(u);
}

__device__ __forceinline__ void mma_tf32(float* d, const uint32_t* a, const uint32_t* b) {
    asm volatile(
        "mma.sync.aligned.m16n8k8.row.col.f32.tf32.tf32.f32 "
        "{%0,%1,%2,%3}, {%4,%5,%6,%7}, {%8,%9}, {%0,%1,%2,%3};\n"
        : "+f"(d[0]), "+f"(d[1]), "+f"(d[2]), "+f"(d[3])
        : "r"(a[0]), "r"(a[1]), "r"(a[2]), "r"(a[3]),
          "r"(b[0]), "r"(b[1]));
}

// ---------------- utility kernels ----------------

__global__ void normalize_rows(const float* __restrict__ in, float* __restrict__ out, int rows) {
    int r = blockIdx.x;
    if (r >= rows) return;
    __shared__ float red[256];
    int t = threadIdx.x;
    float v = (t < Hh) ? in[r*Hh + t] : 0.f;
    red[t] = v*v;
    __syncthreads();
    for (int s = 128; s > 0; s >>= 1) { if (t < s) red[t] += red[t+s]; __syncthreads(); }
    float inv = 1.0f / fmaxf(sqrtf(red[0]), EPSN);
    if (t < Hh) out[r*Hh + t] = v * inv;
}

__global__ void zero_prep() {
    int i = blockIdx.x * blockDim.x + threadIdx.x;
    if (i < Nn) g_degCnt[i] = 0;
    if (i < Rr) g_relCnt[i] = 0;
    if (i == 0) g_zeroCount = 0;
}

// smem-privatized relation histogram + global deg histogram (grid-stride)
__global__ void hist_kernel(const int* __restrict__ er, const int* __restrict__ ds) {
    __shared__ int sh[Rr];
    for (int i = threadIdx.x; i < Rr; i += blockDim.x) sh[i] = 0;
    __syncthreads();
    for (int e = blockIdx.x * blockDim.x + threadIdx.x; e < Ee; e += gridDim.x * blockDim.x) {
        atomicAdd(&sh[er[e]], 1);
        atomicAdd(&g_degCnt[ds[e]], 1);
    }
    __syncthreads();
    for (int i = threadIdx.x; i < Rr; i += blockDim.x)
        if (sh[i]) atomicAdd(&g_relCnt[i], sh[i]);
}

// parallel scan of relation counts (1 block, 512 threads)
__global__ void scan_rel_k() {
    __shared__ int sm[512];
    int t = threadIdx.x;
    int v = (t < Rr) ? g_relCnt[t] : 0;
    sm[t] = v;
    __syncthreads();
    for (int o = 1; o < 512; o <<= 1) {
        int y = (t >= o) ? sm[t-o] : 0;
        __syncthreads();
        sm[t] += y;
        __syncthreads();
    }
    if (t < Rr) { int e = sm[t] - v; g_relBase[t] = e; g_relCur[t] = e; }
    if (t == 0) g_relBase[Rr] = Ee;
}

// two-level node degree scan
__global__ void scan_node_a() {
    int b = blockIdx.x, t = threadIdx.x, i = b*256 + t;
    int v = (i < Nn) ? g_degCnt[i] : 0;
    int lane = t & 31, w = t >> 5;
    int s = v;
#pragma unroll
    for (int o = 1; o < 32; o <<= 1) {
        int y = __shfl_up_sync(0xffffffffu, s, o);
        if (lane >= o) s += y;
    }
    __shared__ int wsum[8];
    if (lane == 31) wsum[w] = s;
    __syncthreads();
    if (w == 0 && lane < 8) {
        int x = wsum[lane];
#pragma unroll
        for (int o = 1; o < 8; o <<= 1) {
            int y = __shfl_up_sync(0xffu, x, o);
            if (lane >= o) x += y;
        }
        wsum[lane] = x;
    }
    __syncthreads();
    int incl = s + (w > 0 ? wsum[w-1] : 0);
    if (i < Nn) g_nodeBase[i] = incl - v;
    if (t == 255) g_blkSum[b] = incl;
}

__global__ void scan_node_b() {
    __shared__ int sm[128];
    int t = threadIdx.x;
    int v = (t < NBLK) ? g_blkSum[t] : 0;
    sm[t] = v;
    __syncthreads();
    for (int o = 1; o < 128; o <<= 1) {
        int y = (t >= o) ? sm[t-o] : 0;
        __syncthreads();
        sm[t] += y;
        __syncthreads();
    }
    if (t < NBLK) g_blkOff[t] = sm[t] - v;
}

__global__ void scan_node_c() {
    int b = blockIdx.x, i = b*256 + threadIdx.x;
    if (i < Nn) {
        int x = g_nodeBase[i] + g_blkOff[b];
        g_nodeBase[i] = x;
        g_nodeCur[i] = x;
    }
    if (i == 0) g_nodeBase[Nn] = Ee;
}

__global__ void scatter_edges(const int* __restrict__ er, const int* __restrict__ ds) {
    int e = blockIdx.x * blockDim.x + threadIdx.x;
    if (e < Ee) {
        int p1 = atomicAdd(&g_relCur[er[e]], 1);
        g_edgeByRel[p1] = e;
        int p2 = atomicAdd(&g_nodeCur[ds[e]], 1);
        g_edgeByDst[p2] = e;
    }
}

__global__ void build_misc() {
    int n = blockIdx.x * blockDim.x + threadIdx.x;
    if (n < Nn) {
        int d = g_degCnt[n];
        g_rnorm[n] = d > 0 ? 1.0f / (float)d : 0.0f;
        if (d == 0) {
            int i = atomicAdd(&g_zeroCount, 1);
            g_zeroList[i] = n;
        }
    }
}

__global__ void rel_mean(const int* __restrict__ srcT, const float* __restrict__ ent) {
    __shared__ int ss[256];
    int r = blockIdx.x, t = threadIdx.x;
    int b0 = g_relBase[r], b1 = g_relBase[r+1];
    float acc = 0.f;
    for (int cb = b0; cb < b1; cb += 256) {
        int m = min(256, b1 - cb);
        if (t < m) ss[t] = srcT[g_edgeByRel[cb + t]];
        __syncthreads();
        if (t < Hh) {
            int i = 0;
            for (; i + 3 < m; i += 4) {
                float a0 = ent[ss[i  ]*Hh + t];
                float a1 = ent[ss[i+1]*Hh + t];
                float a2 = ent[ss[i+2]*Hh + t];
                float a3 = ent[ss[i+3]*Hh + t];
                acc += a0 + a1 + a2 + a3;
            }
            for (; i < m; i++) acc += ent[ss[i]*Hh + t];
        }
        __syncthreads();
    }
    if (t < Hh) {
        int cnt = b1 - b0;
        g_relent[r*Hh + t] = cnt > 0 ? acc / (float)cnt : 0.f;
    }
}

__global__ void build_x(const float* __restrict__ rel_embeds) {
    int i = blockIdx.x * blockDim.x + threadIdx.x;
    if (i < Rr*2*Hh) {
        int r = i / (2*Hh), c = i % (2*Hh);
        g_x[i] = (c < Hh) ? rel_embeds[r*Hh + c] : g_relent[r*Hh + (c - Hh)];
    }
}

__global__ void gru_gate() {
    int r = blockIdx.x, t = threadIdx.x;
    __shared__ float red[256];
    float hp = 0.f;
    if (t < Hh) {
        const float* gi = &g_gi[r*3*Hh];
        const float* gh = &g_gh[r*3*Hh];
        float h  = g_relh[r*Hh + t];
        float rr = 1.f / (1.f + expf(-(gi[t]        + gh[t])));
        float z  = 1.f / (1.f + expf(-(gi[Hh+t]     + gh[Hh+t])));
        float n  = tanhf(gi[2*Hh+t] + rr * gh[2*Hh+t]);
        hp = (1.f - z) * n + z * h;
    }
    red[t] = hp*hp;
    __syncthreads();
    for (int s = 128; s > 0; s >>= 1) { if (t < s) red[t] += red[t+s]; __syncthreads(); }
    float inv = 1.0f / fmaxf(sqrtf(red[0]), EPSN);
    if (t < Hh) g_nrel[r*Hh + t] = hp * inv;
}

__global__ void gather_pre(const int* __restrict__ srcT, const int* __restrict__ erelT,
                           const float* __restrict__ hin) {
    __shared__ int ss[64];
    __shared__ int rs[64];
    int n = blockIdx.x, t = threadIdx.x;
    int b0 = g_nodeBase[n], b1 = g_nodeBase[n+1];
    float acc = 0.f;
    for (int cb = b0; cb < b1; cb += 64) {
        int m = min(64, b1 - cb);
        if (t < m) {
            int e = g_edgeByDst[cb + t];
            ss[t] = srcT[e];
            rs[t] = erelT[e];
        }
        __syncthreads();
        if (t < Hh) {
            for (int i = 0; i < m; i++)
                acc += hin[ss[i]*Hh + t] + g_nrel[rs[i]*Hh + t];
        }
        __syncthreads();
    }
    if (t < Hh) g_pre[n*Hh + t] = acc;
}

__global__ void fixup_zero(const float* __restrict__ Wel, const float* __restrict__ hin,
                           float* __restrict__ hout) {
    __shared__ float hrow[Hh];
    for (int li = blockIdx.x; li < g_zeroCount; li += gridDim.x) {
        int n = g_zeroList[li];
        int t = threadIdx.x;
        if (t < Hh) hrow[t] = hin[n*Hh + t];
        __syncthreads();
        if (t < Hh) {
            float s = 0.f;
            for (int k = 0; k < Hh; k++) s += hrow[k] * Wel[t*Hh + k];
            hout[n*Hh + t] = s >= 0.f ? s : SLOPEC * s;
        }
        __syncthreads();
    }
}

__global__ void rownorm_inv() {
    int row = blockIdx.x * 8 + (threadIdx.x >> 5);
    int lane = threadIdx.x & 31;
    if (row >= Nn) return;
    float s = 0.f;
    for (int c = lane; c < Hh; c += 32) { float v = g_h2[row*Hh + c]; s += v*v; }
    for (int o = 16; o > 0; o >>= 1) s += __shfl_xor_sync(0xffffffff, s, o);
    if (lane == 0) g_winv[row] = 1.0f / fmaxf(sqrtf(s), EPSN);
}

__global__ void copy_relh() {
    int i = blockIdx.x * blockDim.x + threadIdx.x;
    if (i < Rr*Hh) g_relh[i] = g_nrel[i];
}

// ---------------- tf32 tensor-core GEMM: C = epi(A @ W^T) ----------------
// A: (M,K) row-major. W: (Nout,K) row-major. C: (M,Nout) row-major.
// Block tile 128x128, 256 threads (8 warps, 2x4), warp tile 64x32, BK=16.
// EPI: 0 plain | 1 rrelu(rowscale[row]*acc + Sadd) | 4 acc+bias
//      5 fused gate-update: u=sigmoid(acc+bias[col]);
//        e=A[row*K+col]; w=Sadd[row*Nout+col]*rowscale[row]; out=e+u*(w-e)
// SPLIT>1: grid.z splits K into chunks of klen; raw partials to C[z*M*Nout+..]
#define TPAD 136
template<int EPI, int SPLIT>
__global__ void __launch_bounds__(256)
tgemm(const float* __restrict__ A, const float* __restrict__ W,
      float* __restrict__ C, int M, int Nout, int Kdim, int klen,
      const float* __restrict__ bias,
      const float* __restrict__ Sadd,
      const float* __restrict__ rowscale) {
    __shared__ float As[16][TPAD];
    __shared__ float Ws[16][TPAD];
    int tid = threadIdx.x;
    int j0 = blockIdx.x * 128;
    int i0 = blockIdx.y * 128;
    int k0 = (SPLIT > 1) ? blockIdx.z * klen : 0;
    int k1 = (SPLIT > 1) ? min(Kdim, k0 + klen) : Kdim;

    int wid = tid >> 5, lane = tid & 31;
    int wr = wid & 1, wc = wid >> 1;        // 2 warp-rows x 4 warp-cols
    int gid = lane >> 2, tig = lane & 3;

    float acc[4][4][4];
#pragma unroll
    for (int a = 0; a < 4; a++)
#pragma unroll
        for (int b = 0; b < 4; b++)
#pragma unroll
            for (int v = 0; v < 4; v++) acc[a][b][v] = 0.f;

    int arow = tid >> 1;                   // 0..127
    int akoff = (tid & 1) * 8;             // 0 or 8
    int gr = i0 + arow;
    int gw = j0 + arow;
    bool rok = gr < M;
    bool wok = gw < Nout;
    const float* Arow_p = A + (size_t)gr * Kdim;
    const float* Wrow_p = W + (size_t)gw * Kdim;

    for (int kt = k0; kt < k1; kt += 16) {
        int gka = kt + akoff;
        if (rok && gka + 8 <= k1) {
            float4 v0 = *reinterpret_cast<const float4*>(Arow_p + gka);
            float4 v1 = *reinterpret_cast<const float4*>(Arow_p + gka + 4);
            As[akoff+0][arow] = to_tf32(v0.x); As[akoff+1][arow] = to_tf32(v0.y);
            As[akoff+2][arow] = to_tf32(v0.z); As[akoff+3][arow] = to_tf32(v0.w);
            As[akoff+4][arow] = to_tf32(v1.x); As[akoff+5][arow] = to_tf32(v1.y);
            As[akoff+6][arow] = to_tf32(v1.z); As[akoff+7][arow] = to_tf32(v1.w);
        } else {
#pragma unroll
            for (int q = 0; q < 8; q++)
                As[akoff+q][arow] = (rok && gka + q < k1) ? to_tf32(Arow_p[gka + q]) : 0.f;
        }
        if (wok && gka + 8 <= k1) {
            float4 v0 = *reinterpret_cast<const float4*>(Wrow_p + gka);
            float4 v1 = *reinterpret_cast<const float4*>(Wrow_p + gka + 4);
            Ws[akoff+0][arow] = to_tf32(v0.x); Ws[akoff+1][arow] = to_tf32(v0.y);
            Ws[akoff+2][arow] = to_tf32(v0.z); Ws[akoff+3][arow] = to_tf32(v0.w);
            Ws[akoff+4][arow] = to_tf32(v1.x); Ws[akoff+5][arow] = to_tf32(v1.y);
            Ws[akoff+6][arow] = to_tf32(v1.z); Ws[akoff+7][arow] = to_tf32(v1.w);
        } else {
#pragma unroll
            for (int q = 0; q < 8; q++)
                Ws[akoff+q][arow] = (wok && gka + q < k1) ? to_tf32(Wrow_p[gka + q]) : 0.f;
        }
        __syncthreads();
#pragma unroll
        for (int kk = 0; kk < 16; kk += 8) {
            uint32_t af[4][4];
            uint32_t bf[4][2];
#pragma unroll
            for (int mt = 0; mt < 4; mt++) {
                int r0 = wr*64 + mt*16 + gid;
                af[mt][0] = __float_as_uint(As[kk+tig  ][r0]);
                af[mt][1] = __float_as_uint(As[kk+tig  ][r0+8]);
                af[mt][2] = __float_as_uint(As[kk+tig+4][r0]);
                af[mt][3] = __float_as_uint(As[kk+tig+4][r0+8]);
            }
#pragma unroll
            for (int nt = 0; nt < 4; nt++) {
                int cn = wc*32 + nt*8 + gid;
                bf[nt][0] = __float_as_uint(Ws[kk+tig  ][cn]);
                bf[nt][1] = __float_as_uint(Ws[kk+tig+4][cn]);
            }
#pragma unroll
            for (int mt = 0; mt < 4; mt++)
#pragma unroll
                for (int nt = 0; nt < 4; nt++)
                    mma_tf32(acc[mt][nt], af[mt], bf[nt]);
        }
        __syncthreads();
    }

    float* Cb = (SPLIT > 1) ? C + (size_t)blockIdx.z * M * Nout : C;
#pragma unroll
    for (int mt = 0; mt < 4; mt++) {
#pragma unroll
        for (int nt = 0; nt < 4; nt++) {
            int rbase = i0 + wr*64 + mt*16 + gid;
            int cbase = j0 + wc*32 + nt*8 + tig*2;
#pragma unroll
            for (int v = 0; v < 4; v++) {
                int row = rbase + ((v >= 2) ? 8 : 0);
                int col = cbase + (v & 1);
                if (row >= M || col >= Nout) continue;
                float x = acc[mt][nt][v];
                if (EPI == 1) {
                    x = x * rowscale[row] + Sadd[(size_t)row * Nout + col];
                    x = x >= 0.f ? x : SLOPEC * x;
                } else if (EPI == 4) {
                    x += bias[col];
                } else if (EPI == 5) {
                    float u = 1.f / (1.f + expf(-(x + bias[col])));
                    float e = A[(size_t)row * Kdim + col];
                    float w = Sadd[(size_t)row * Nout + col] * rowscale[row];
                    x = e + u * (w - e);
                }
                Cb[(size_t)row * Nout + col] = x;
            }
        }
    }
}

// deterministic split-K reduction + bias + relu  (fc decoder output)
__global__ void split_reduce_relu(float* __restrict__ dst, const float* __restrict__ bias) {
    int i = blockIdx.x * blockDim.x + threadIdx.x;
    if (i < Bb*Hh) {
        float s = 0.f;
#pragma unroll
        for (int z = 0; z < KSPLIT; z++) s += g_part[(size_t)z * Bb * Hh + i];
        s += bias[i % Hh];
        dst[i] = fmaxf(s, 0.f);
    }
}

// ---------------- decoder ----------------

__global__ void dec_gather(const int* __restrict__ sidx, const int* __restrict__ oidx,
                           const float* __restrict__ ent, int mode) {
    int i = blockIdx.x * blockDim.x + threadIdx.x;
    if (i < Bb*Hh) {
        int b = i / Hh, c = i % Hh;
        g_e1[i] = ent[sidx[b]*Hh + c];
        g_e2[i] = mode ? ent[oidx[b]*Hh + c] : g_relh[oidx[b]*Hh + c];
    }
}

__global__ void conv_feat(const float* __restrict__ cw, const float* __restrict__ cb) {
    int b = blockIdx.x;
    __shared__ float s1[Hh+2], s2[Hh+2];
    __shared__ float w[Cc*6];
    __shared__ float bb[Cc];
    int t = threadIdx.x;
    if (t < Hh) { s1[t+1] = g_e1[b*Hh + t]; s2[t+1] = g_e2[b*Hh + t]; }
    if (t == 0) { s1[0] = 0.f; s2[0] = 0.f; s1[Hh+1] = 0.f; s2[Hh+1] = 0.f; }
    for (int i = t; i < Cc*6; i += blockDim.x) w[i] = cw[i];
    if (t < Cc) bb[t] = cb[t];
    __syncthreads();
    for (int idx = t; idx < CH; idx += blockDim.x) {
        int c = idx / Hh, i = idx % Hh;
        const float* wc = &w[c*6];
        float v = bb[c]
            + s1[i]*wc[0] + s1[i+1]*wc[1] + s1[i+2]*wc[2]
            + s2[i]*wc[3] + s2[i+1]*wc[4] + s2[i+2]*wc[5];
        g_feat[(size_t)b*CH + idx] = fmaxf(v, 0.f);
    }
}

// ---------------- host ----------------

static void* symaddr(const void* s) { void* p = nullptr; cudaGetSymbolAddress(&p, s); return p; }

extern "C" void kernel_launch(void* const* d_in, const int* in_sizes, int n_in,
                              void* d_out, int out_size) {
    const float* ent_embeds = (const float*)d_in[0];
    const float* rel_embeds = (const float*)d_in[1];
    const float* Wr1  = (const float*)d_in[2];
    const float* Wsl1 = (const float*)d_in[3];
    const float* Wel1 = (const float*)d_in[4];
    const float* Wr2  = (const float*)d_in[5];
    const float* Wsl2 = (const float*)d_in[6];
    const float* Wel2 = (const float*)d_in[7];
    const float* lin_W = (const float*)d_in[8];
    const float* lin_b = (const float*)d_in[9];
    const float* gru_Wih = (const float*)d_in[10];
    const float* gru_Whh = (const float*)d_in[11];
    const float* gru_bih = (const float*)d_in[12];
    const float* gru_bhh = (const float*)d_in[13];
    const float* conve_w = (const float*)d_in[14];
    const float* conve_b = (const float*)d_in[15];
    const float* fce_w = (const float*)d_in[16];
    const float* fce_b = (const float*)d_in[17];
    const float* convr_w = (const float*)d_in[18];
    const float* convr_b = (const float*)d_in[19];
    const float* fcr_w = (const float*)d_in[20];
    const float* fcr_b = (const float*)d_in[21];
    const int* src  = (const int*)d_in[22];
    const int* dst  = (const int*)d_in[23];
    const int* erel = (const int*)d_in[24];
    const int* subj = (const int*)d_in[25];
    const int* relI = (const int*)d_in[26];
    const int* objI = (const int*)d_in[27];
    float* out = (float*)d_out;

    float* p_entA  = (float*)symaddr(g_ent);
    float* p_entB  = (float*)symaddr(g_entB);
    float* p_h1    = (float*)symaddr(g_h1);
    float* p_h2    = (float*)symaddr(g_h2);
    float* p_pre   = (float*)symaddr(g_pre);
    float* p_S     = (float*)symaddr(g_S);
    float* p_winv  = (float*)symaddr(g_winv);
    float* p_rnorm = (float*)symaddr(g_rnorm);
    float* p_relh  = (float*)symaddr(g_relh);
    float* p_x     = (float*)symaddr(g_x);
    float* p_gi    = (float*)symaddr(g_gi);
    float* p_gh    = (float*)symaddr(g_gh);
    float* p_feat  = (float*)symaddr(g_feat);
    float* p_dec   = (float*)symaddr(g_dec);
    float* p_part  = (float*)symaddr(g_part);

    normalize_rows<<<Nn, 256>>>(ent_embeds, p_entA, Nn);
    normalize_rows<<<Rr, 256>>>(rel_embeds, p_relh, Rr);

    const float* Wr_[2]  = {Wr1, Wr2};
    const float* Wsl_[2] = {Wsl1, Wsl2};
    const float* Wel_[2] = {Wel1, Wel2};

    #define TGX(Nc) (((Nc)+127)/128)
    #define TGY(Mr) (((Mr)+127)/128)

    float* entIn = p_entA;
    float* entOut = p_entB;

    for (int t = 0; t < Tt; t++) {
        const int* srcT  = src  + t*Ee;
        const int* dstT  = dst  + t*Ee;
        const int* erelT = erel + t*Ee;

        zero_prep<<<(Nn + 255)/256, 256>>>();
        hist_kernel<<<160, 256>>>(erelT, dstT);
        scan_rel_k<<<1, 512>>>();
        scan_node_a<<<NBLK, 256>>>();
        scan_node_b<<<1, 128>>>();
        scan_node_c<<<NBLK, 256>>>();
        scatter_edges<<<(Ee + 255)/256, 256>>>(erelT, dstT);
        build_misc<<<(Nn + 255)/256, 256>>>();

        // relation-level GRU
        rel_mean<<<Rr, 256>>>(srcT, entIn);
        build_x<<<(Rr*2*Hh + 255)/256, 256>>>(rel_embeds);
        tgemm<4,1><<<dim3(TGX(3*Hh), TGY(Rr)), 256>>>(p_x, gru_Wih, p_gi, Rr, 3*Hh, 2*Hh, 0, gru_bih, nullptr, nullptr);
        tgemm<4,1><<<dim3(TGX(3*Hh), TGY(Rr)), 256>>>(p_relh, gru_Whh, p_gh, Rr, 3*Hh, Hh, 0, gru_bhh, nullptr, nullptr);
        gru_gate<<<Rr, 256>>>();

        // two RGCN layers (scatter-then-GEMM factorization)
        for (int l = 0; l < 2; l++) {
            const float* hin = (l == 0) ? entIn : p_h1;
            float* hout = (l == 0) ? p_h1 : p_h2;
            gather_pre<<<Nn, 256>>>(srcT, erelT, hin);
            tgemm<0,1><<<dim3(TGX(Hh), TGY(Nn)), 256>>>(hin, Wsl_[l], p_S, Nn, Hh, Hh, 0, nullptr, nullptr, nullptr);
            tgemm<1,1><<<dim3(TGX(Hh), TGY(Nn)), 256>>>(p_pre, Wr_[l], hout, Nn, Hh, Hh, 0, nullptr, p_S, p_rnorm);
            fixup_zero<<<64, 256>>>(Wel_[l], hin, hout);
        }

        // entity update: fused sigmoid-gate GEMM writes entOut
        rownorm_inv<<<(Nn + 7)/8, 256>>>();
        tgemm<5,1><<<dim3(TGX(Hh), TGY(Nn)), 256>>>(entIn, lin_W, entOut, Nn, Hh, Hh, 0, lin_b, p_h2, p_winv);
        copy_relh<<<(Rr*Hh + 255)/256, 256>>>();

        float* tmp = entIn; entIn = entOut; entOut = tmp;
    }
    // after swap, entIn points at the final entity embeddings
    float* entF = entIn;

    const int klen = CH / KSPLIT;   // 1000

    // ---- decoder: obj logits ----
    dec_gather<<<(Bb*Hh + 255)/256, 256>>>(subj, relI, entF, 0);
    conv_feat<<<Bb, 256>>>(conve_w, conve_b);
    tgemm<0,KSPLIT><<<dim3(TGX(Hh), TGY(Bb), KSPLIT), 256>>>(p_feat, fce_w, p_part, Bb, Hh, CH, klen, nullptr, nullptr, nullptr);
    split_reduce_relu<<<(Bb*Hh + 255)/256, 256>>>(p_dec, fce_b);
    tgemm<0,1><<<dim3(TGX(Nn), TGY(Bb)), 256>>>(p_dec, entF, out, Bb, Nn, Hh, 0, nullptr, nullptr, nullptr);

    // ---- decoder: rel logits ----
    dec_gather<<<(Bb*Hh + 255)/256, 256>>>(subj, objI, entF, 1);
    conv_feat<<<Bb, 256>>>(convr_w, convr_b);
    tgemm<0,KSPLIT><<<dim3(TGX(Hh), TGY(Bb), KSPLIT), 256>>>(p_feat, fcr_w, p_part, Bb, Hh, CH, klen, nullptr, nullptr, nullptr);
    split_reduce_relu<<<(Bb*Hh + 255)/256, 256>>>(p_dec, fcr_b);
    tgemm<0,1><<<dim3(TGX(Rr), TGY(Bb)), 256>>>(p_dec, p_relh, out + (size_t)Bb*Nn, Bb, Rr, Hh, 0, nullptr, nullptr, nullptr);
}

// round 5
// speedup vs baseline: 2.4549x; 1.0005x over previous
#include <cuda_runtime.h>
#include <math.h>
#include <stdint.h>

#define Nn 20000
#define Rr 400
#define Hh 200
#define Ee 200000
#define Tt 3
#define Bb 1024
#define Cc 50
#define CH (Cc*Hh)
#define KSPLIT 10
#define NBLK ((Nn + 255) / 256)
#define SLOPEC 0.22916666666666666f
#define EPSN 1e-12f

// ---------------- scratch (device globals; no allocation allowed) ----------------
__device__ float g_ent[Nn*Hh];
__device__ float g_entB[Nn*Hh];
__device__ float g_h1[Nn*Hh];
__device__ float g_h2[Nn*Hh];
__device__ float g_pre[Nn*Hh];
__device__ float g_S[Nn*Hh];
__device__ float g_winv[Nn];
__device__ float g_rnorm[Nn];
__device__ float g_relh[Rr*Hh];
__device__ float g_relent[Rr*Hh];
__device__ float g_x[Rr*2*Hh];
__device__ float g_gi[Rr*3*Hh];
__device__ float g_gh[Rr*3*Hh];
__device__ float g_nrel[Rr*Hh];
__device__ int   g_relCnt[Rr];
__device__ int   g_relBase[Rr+1];
__device__ int   g_relCur[Rr];
__device__ int   g_edgeByRel[Ee];
__device__ int   g_degCnt[Nn];
__device__ int   g_nodeBase[Nn+1];
__device__ int   g_nodeCur[Nn];
__device__ int   g_edgeByDst[Ee];
__device__ int   g_blkSum[NBLK];
__device__ int   g_blkOff[NBLK];
__device__ int   g_zeroList[Nn];
__device__ int   g_zeroCount;
__device__ float g_feat[Bb*CH];
__device__ float g_dec[Bb*Hh];
__device__ float g_e1[Bb*Hh];
__device__ float g_e2[Bb*Hh];
__device__ float g_part[KSPLIT*Bb*Hh];

// ---------------- tf32 helpers ----------------
__device__ __forceinline__ float to_tf32(float x) {
    uint32_t u;
    asm("cvt.rna.tf32.f32 %0, %1;" : "=r"(u) : "r"(__float_as_uint(x)));
    return __uint_as_float(u);
}

__device__ __forceinline__ void mma_tf32(float* d, const uint32_t* a, const uint32_t* b) {
    asm volatile(
        "mma.sync.aligned.m16n8k8.row.col.f32.tf32.tf32.f32 "
        "{%0,%1,%2,%3}, {%4,%5,%6,%7}, {%8,%9}, {%0,%1,%2,%3};\n"
        : "+f"(d[0]), "+f"(d[1]), "+f"(d[2]), "+f"(d[3])
        : "r"(a[0]), "r"(a[1]), "r"(a[2]), "r"(a[3]),
          "r"(b[0]), "r"(b[1]));
}

// ---------------- utility kernels ----------------

__global__ void normalize_rows(const float* __restrict__ in, float* __restrict__ out, int rows) {
    int r = blockIdx.x;
    if (r >= rows) return;
    __shared__ float red[256];
    int t = threadIdx.x;
    float v = (t < Hh) ? in[r*Hh + t] : 0.f;
    red[t] = v*v;
    __syncthreads();
    for (int s = 128; s > 0; s >>= 1) { if (t < s) red[t] += red[t+s]; __syncthreads(); }
    float inv = 1.0f / fmaxf(sqrtf(red[0]), EPSN);
    if (t < Hh) out[r*Hh + t] = v * inv;
}

__global__ void zero_prep() {
    int i = blockIdx.x * blockDim.x + threadIdx.x;
    if (i < Nn) g_degCnt[i] = 0;
    if (i < Rr) g_relCnt[i] = 0;
    if (i == 0) g_zeroCount = 0;
}

// smem-privatized relation histogram + global deg histogram (grid-stride)
__global__ void hist_kernel(const int* __restrict__ er, const int* __restrict__ ds) {
    __shared__ int sh[Rr];
    for (int i = threadIdx.x; i < Rr; i += blockDim.x) sh[i] = 0;
    __syncthreads();
    for (int e = blockIdx.x * blockDim.x + threadIdx.x; e < Ee; e += gridDim.x * blockDim.x) {
        atomicAdd(&sh[er[e]], 1);
        atomicAdd(&g_degCnt[ds[e]], 1);
    }
    __syncthreads();
    for (int i = threadIdx.x; i < Rr; i += blockDim.x)
        if (sh[i]) atomicAdd(&g_relCnt[i], sh[i]);
}

// parallel scan of relation counts (1 block, 512 threads)
__global__ void scan_rel_k() {
    __shared__ int sm[512];
    int t = threadIdx.x;
    int v = (t < Rr) ? g_relCnt[t] : 0;
    sm[t] = v;
    __syncthreads();
    for (int o = 1; o < 512; o <<= 1) {
        int y = (t >= o) ? sm[t-o] : 0;
        __syncthreads();
        sm[t] += y;
        __syncthreads();
    }
    if (t < Rr) { int e = sm[t] - v; g_relBase[t] = e; g_relCur[t] = e; }
    if (t == 0) g_relBase[Rr] = Ee;
}

// two-level node degree scan
__global__ void scan_node_a() {
    int b = blockIdx.x, t = threadIdx.x, i = b*256 + t;
    int v = (i < Nn) ? g_degCnt[i] : 0;
    int lane = t & 31, w = t >> 5;
    int s = v;
#pragma unroll
    for (int o = 1; o < 32; o <<= 1) {
        int y = __shfl_up_sync(0xffffffffu, s, o);
        if (lane >= o) s += y;
    }
    __shared__ int wsum[8];
    if (lane == 31) wsum[w] = s;
    __syncthreads();
    if (w == 0 && lane < 8) {
        int x = wsum[lane];
#pragma unroll
        for (int o = 1; o < 8; o <<= 1) {
            int y = __shfl_up_sync(0xffu, x, o);
            if (lane >= o) x += y;
        }
        wsum[lane] = x;
    }
    __syncthreads();
    int incl = s + (w > 0 ? wsum[w-1] : 0);
    if (i < Nn) g_nodeBase[i] = incl - v;
    if (t == 255) g_blkSum[b] = incl;
}

__global__ void scan_node_b() {
    __shared__ int sm[128];
    int t = threadIdx.x;
    int v = (t < NBLK) ? g_blkSum[t] : 0;
    sm[t] = v;
    __syncthreads();
    for (int o = 1; o < 128; o <<= 1) {
        int y = (t >= o) ? sm[t-o] : 0;
        __syncthreads();
        sm[t] += y;
        __syncthreads();
    }
    if (t < NBLK) g_blkOff[t] = sm[t] - v;
}

__global__ void scan_node_c() {
    int b = blockIdx.x, i = b*256 + threadIdx.x;
    if (i < Nn) {
        int x = g_nodeBase[i] + g_blkOff[b];
        g_nodeBase[i] = x;
        g_nodeCur[i] = x;
    }
    if (i == 0) g_nodeBase[Nn] = Ee;
}

__global__ void scatter_edges(const int* __restrict__ er, const int* __restrict__ ds) {
    int e = blockIdx.x * blockDim.x + threadIdx.x;
    if (e < Ee) {
        int p1 = atomicAdd(&g_relCur[er[e]], 1);
        g_edgeByRel[p1] = e;
        int p2 = atomicAdd(&g_nodeCur[ds[e]], 1);
        g_edgeByDst[p2] = e;
    }
}

__global__ void build_misc() {
    int n = blockIdx.x * blockDim.x + threadIdx.x;
    if (n < Nn) {
        int d = g_degCnt[n];
        g_rnorm[n] = d > 0 ? 1.0f / (float)d : 0.0f;
        if (d == 0) {
            int i = atomicAdd(&g_zeroCount, 1);
            g_zeroList[i] = n;
        }
    }
}

__global__ void rel_mean(const int* __restrict__ srcT, const float* __restrict__ ent) {
    __shared__ int ss[256];
    int r = blockIdx.x, t = threadIdx.x;
    int b0 = g_relBase[r], b1 = g_relBase[r+1];
    float acc = 0.f;
    for (int cb = b0; cb < b1; cb += 256) {
        int m = min(256, b1 - cb);
        if (t < m) ss[t] = srcT[g_edgeByRel[cb + t]];
        __syncthreads();
        if (t < Hh) {
            int i = 0;
            for (; i + 3 < m; i += 4) {
                float a0 = ent[ss[i  ]*Hh + t];
                float a1 = ent[ss[i+1]*Hh + t];
                float a2 = ent[ss[i+2]*Hh + t];
                float a3 = ent[ss[i+3]*Hh + t];
                acc += a0 + a1 + a2 + a3;
            }
            for (; i < m; i++) acc += ent[ss[i]*Hh + t];
        }
        __syncthreads();
    }
    if (t < Hh) {
        int cnt = b1 - b0;
        g_relent[r*Hh + t] = cnt > 0 ? acc / (float)cnt : 0.f;
    }
}

__global__ void build_x(const float* __restrict__ rel_embeds) {
    int i = blockIdx.x * blockDim.x + threadIdx.x;
    if (i < Rr*2*Hh) {
        int r = i / (2*Hh), c = i % (2*Hh);
        g_x[i] = (c < Hh) ? rel_embeds[r*Hh + c] : g_relent[r*Hh + (c - Hh)];
    }
}

__global__ void gru_gate() {
    int r = blockIdx.x, t = threadIdx.x;
    __shared__ float red[256];
    float hp = 0.f;
    if (t < Hh) {
        const float* gi = &g_gi[r*3*Hh];
        const float* gh = &g_gh[r*3*Hh];
        float h  = g_relh[r*Hh + t];
        float rr = 1.f / (1.f + expf(-(gi[t]        + gh[t])));
        float z  = 1.f / (1.f + expf(-(gi[Hh+t]     + gh[Hh+t])));
        float n  = tanhf(gi[2*Hh+t] + rr * gh[2*Hh+t]);
        hp = (1.f - z) * n + z * h;
    }
    red[t] = hp*hp;
    __syncthreads();
    for (int s = 128; s > 0; s >>= 1) { if (t < s) red[t] += red[t+s]; __syncthreads(); }
    float inv = 1.0f / fmaxf(sqrtf(red[0]), EPSN);
    if (t < Hh) g_nrel[r*Hh + t] = hp * inv;
}

__global__ void gather_pre(const int* __restrict__ srcT, const int* __restrict__ erelT,
                           const float* __restrict__ hin) {
    __shared__ int ss[64];
    __shared__ int rs[64];
    int n = blockIdx.x, t = threadIdx.x;
    int b0 = g_nodeBase[n], b1 = g_nodeBase[n+1];
    float acc = 0.f;
    for (int cb = b0; cb < b1; cb += 64) {
        int m = min(64, b1 - cb);
        if (t < m) {
            int e = g_edgeByDst[cb + t];
            ss[t] = srcT[e];
            rs[t] = erelT[e];
        }
        __syncthreads();
        if (t < Hh) {
            for (int i = 0; i < m; i++)
                acc += hin[ss[i]*Hh + t] + g_nrel[rs[i]*Hh + t];
        }
        __syncthreads();
    }
    if (t < Hh) g_pre[n*Hh + t] = acc;
}

__global__ void fixup_zero(const float* __restrict__ Wel, const float* __restrict__ hin,
                           float* __restrict__ hout) {
    __shared__ float hrow[Hh];
    for (int li = blockIdx.x; li < g_zeroCount; li += gridDim.x) {
        int n = g_zeroList[li];
        int t = threadIdx.x;
        if (t < Hh) hrow[t] = hin[n*Hh + t];
        __syncthreads();
        if (t < Hh) {
            float s = 0.f;
            for (int k = 0; k < Hh; k++) s += hrow[k] * Wel[t*Hh + k];
            hout[n*Hh + t] = s >= 0.f ? s : SLOPEC * s;
        }
        __syncthreads();
    }
}

__global__ void rownorm_inv() {
    int row = blockIdx.x * 8 + (threadIdx.x >> 5);
    int lane = threadIdx.x & 31;
    if (row >= Nn) return;
    float s = 0.f;
    for (int c = lane; c < Hh; c += 32) { float v = g_h2[row*Hh + c]; s += v*v; }
    for (int o = 16; o > 0; o >>= 1) s += __shfl_xor_sync(0xffffffff, s, o);
    if (lane == 0) g_winv[row] = 1.0f / fmaxf(sqrtf(s), EPSN);
}

__global__ void copy_relh() {
    int i = blockIdx.x * blockDim.x + threadIdx.x;
    if (i < Rr*Hh) g_relh[i] = g_nrel[i];
}

// ---------------- tf32 tensor-core GEMM: C = epi(A @ W^T) ----------------
// A: (M,K) row-major. W: (Nout,K) row-major. C: (M,Nout) row-major.
// Block tile 128x128, 256 threads (8 warps, 2x4), warp tile 64x32, BK=16.
// EPI: 0 plain | 1 rrelu(rowscale[row]*acc + Sadd) | 4 acc+bias
//      5 fused gate-update: u=sigmoid(acc+bias[col]);
//        e=A[row*K+col]; w=Sadd[row*Nout+col]*rowscale[row]; out=e+u*(w-e)
// SPLIT>1: grid.z splits K into chunks of klen; raw partials to C[z*M*Nout+..]
#define TPAD 136
template<int EPI, int SPLIT>
__global__ void __launch_bounds__(256)
tgemm(const float* __restrict__ A, const float* __restrict__ W,
      float* __restrict__ C, int M, int Nout, int Kdim, int klen,
      const float* __restrict__ bias,
      const float* __restrict__ Sadd,
      const float* __restrict__ rowscale) {
    __shared__ float As[16][TPAD];
    __shared__ float Ws[16][TPAD];
    int tid = threadIdx.x;
    int j0 = blockIdx.x * 128;
    int i0 = blockIdx.y * 128;
    int k0 = (SPLIT > 1) ? blockIdx.z * klen : 0;
    int k1 = (SPLIT > 1) ? min(Kdim, k0 + klen) : Kdim;

    int wid = tid >> 5, lane = tid & 31;
    int wr = wid & 1, wc = wid >> 1;        // 2 warp-rows x 4 warp-cols
    int gid = lane >> 2, tig = lane & 3;

    float acc[4][4][4];
#pragma unroll
    for (int a = 0; a < 4; a++)
#pragma unroll
        for (int b = 0; b < 4; b++)
#pragma unroll
            for (int v = 0; v < 4; v++) acc[a][b][v] = 0.f;

    int arow = tid >> 1;                   // 0..127
    int akoff = (tid & 1) * 8;             // 0 or 8
    int gr = i0 + arow;
    int gw = j0 + arow;
    bool rok = gr < M;
    bool wok = gw < Nout;
    const float* Arow_p = A + (size_t)gr * Kdim;
    const float* Wrow_p = W + (size_t)gw * Kdim;

    for (int kt = k0; kt < k1; kt += 16) {
        int gka = kt + akoff;
        if (rok && gka + 8 <= k1) {
            float4 v0 = *reinterpret_cast<const float4*>(Arow_p + gka);
            float4 v1 = *reinterpret_cast<const float4*>(Arow_p + gka + 4);
            As[akoff+0][arow] = to_tf32(v0.x); As[akoff+1][arow] = to_tf32(v0.y);
            As[akoff+2][arow] = to_tf32(v0.z); As[akoff+3][arow] = to_tf32(v0.w);
            As[akoff+4][arow] = to_tf32(v1.x); As[akoff+5][arow] = to_tf32(v1.y);
            As[akoff+6][arow] = to_tf32(v1.z); As[akoff+7][arow] = to_tf32(v1.w);
        } else {
#pragma unroll
            for (int q = 0; q < 8; q++)
                As[akoff+q][arow] = (rok && gka + q < k1) ? to_tf32(Arow_p[gka + q]) : 0.f;
        }
        if (wok && gka + 8 <= k1) {
            float4 v0 = *reinterpret_cast<const float4*>(Wrow_p + gka);
            float4 v1 = *reinterpret_cast<const float4*>(Wrow_p + gka + 4);
            Ws[akoff+0][arow] = to_tf32(v0.x); Ws[akoff+1][arow] = to_tf32(v0.y);
            Ws[akoff+2][arow] = to_tf32(v0.z); Ws[akoff+3][arow] = to_tf32(v0.w);
            Ws[akoff+4][arow] = to_tf32(v1.x); Ws[akoff+5][arow] = to_tf32(v1.y);
            Ws[akoff+6][arow] = to_tf32(v1.z); Ws[akoff+7][arow] = to_tf32(v1.w);
        } else {
#pragma unroll
            for (int q = 0; q < 8; q++)
                Ws[akoff+q][arow] = (wok && gka + q < k1) ? to_tf32(Wrow_p[gka + q]) : 0.f;
        }
        __syncthreads();
#pragma unroll
        for (int kk = 0; kk < 16; kk += 8) {
            uint32_t af[4][4];
            uint32_t bf[4][2];
#pragma unroll
            for (int mt = 0; mt < 4; mt++) {
                int r0 = wr*64 + mt*16 + gid;
                af[mt][0] = __float_as_uint(As[kk+tig  ][r0]);
                af[mt][1] = __float_as_uint(As[kk+tig  ][r0+8]);
                af[mt][2] = __float_as_uint(As[kk+tig+4][r0]);
                af[mt][3] = __float_as_uint(As[kk+tig+4][r0+8]);
            }
#pragma unroll
            for (int nt = 0; nt < 4; nt++) {
                int cn = wc*32 + nt*8 + gid;
                bf[nt][0] = __float_as_uint(Ws[kk+tig  ][cn]);
                bf[nt][1] = __float_as_uint(Ws[kk+tig+4][cn]);
            }
#pragma unroll
            for (int mt = 0; mt < 4; mt++)
#pragma unroll
                for (int nt = 0; nt < 4; nt++)
                    mma_tf32(acc[mt][nt], af[mt], bf[nt]);
        }
        __syncthreads();
    }

    float* Cb = (SPLIT > 1) ? C + (size_t)blockIdx.z * M * Nout : C;
#pragma unroll
    for (int mt = 0; mt < 4; mt++) {
#pragma unroll
        for (int nt = 0; nt < 4; nt++) {
            int rbase = i0 + wr*64 + mt*16 + gid;
            int cbase = j0 + wc*32 + nt*8 + tig*2;
#pragma unroll
            for (int v = 0; v < 4; v++) {
                int row = rbase + ((v >= 2) ? 8 : 0);
                int col = cbase + (v & 1);
                if (row >= M || col >= Nout) continue;
                float x = acc[mt][nt][v];
                if (EPI == 1) {
                    x = x * rowscale[row] + Sadd[(size_t)row * Nout + col];
                    x = x >= 0.f ? x : SLOPEC * x;
                } else if (EPI == 4) {
                    x += bias[col];
                } else if (EPI == 5) {
                    float u = 1.f / (1.f + expf(-(x + bias[col])));
                    float e = A[(size_t)row * Kdim + col];
                    float w = Sadd[(size_t)row * Nout + col] * rowscale[row];
                    x = e + u * (w - e);
                }
                Cb[(size_t)row * Nout + col] = x;
            }
        }
    }
}

// deterministic split-K reduction + bias + relu  (fc decoder output)
__global__ void split_reduce_relu(float* __restrict__ dst, const float* __restrict__ bias) {
    int i = blockIdx.x * blockDim.x + threadIdx.x;
    if (i < Bb*Hh) {
        float s = 0.f;
#pragma unroll
        for (int z = 0; z < KSPLIT; z++) s += g_part[(size_t)z * Bb * Hh + i];
        s += bias[i % Hh];
        dst[i] = fmaxf(s, 0.f);
    }
}

// ---------------- decoder ----------------

__global__ void dec_gather(const int* __restrict__ sidx, const int* __restrict__ oidx,
                           const float* __restrict__ ent, int mode) {
    int i = blockIdx.x * blockDim.x + threadIdx.x;
    if (i < Bb*Hh) {
        int b = i / Hh, c = i % Hh;
        g_e1[i] = ent[sidx[b]*Hh + c];
        g_e2[i] = mode ? ent[oidx[b]*Hh + c] : g_relh[oidx[b]*Hh + c];
    }
}

__global__ void conv_feat(const float* __restrict__ cw, const float* __restrict__ cb) {
    int b = blockIdx.x;
    __shared__ float s1[Hh+2], s2[Hh+2];
    __shared__ float w[Cc*6];
    __shared__ float bb[Cc];
    int t = threadIdx.x;
    if (t < Hh) { s1[t+1] = g_e1[b*Hh + t]; s2[t+1] = g_e2[b*Hh + t]; }
    if (t == 0) { s1[0] = 0.f; s2[0] = 0.f; s1[Hh+1] = 0.f; s2[Hh+1] = 0.f; }
    for (int i = t; i < Cc*6; i += blockDim.x) w[i] = cw[i];
    if (t < Cc) bb[t] = cb[t];
    __syncthreads();
    for (int idx = t; idx < CH; idx += blockDim.x) {
        int c = idx / Hh, i = idx % Hh;
        const float* wc = &w[c*6];
        float v = bb[c]
            + s1[i]*wc[0] + s1[i+1]*wc[1] + s1[i+2]*wc[2]
            + s2[i]*wc[3] + s2[i+1]*wc[4] + s2[i+2]*wc[5];
        g_feat[(size_t)b*CH + idx] = fmaxf(v, 0.f);
    }
}

// ---------------- host ----------------

static void* symaddr(const void* s) { void* p = nullptr; cudaGetSymbolAddress(&p, s); return p; }

extern "C" void kernel_launch(void* const* d_in, const int* in_sizes, int n_in,
                              void* d_out, int out_size) {
    const float* ent_embeds = (const float*)d_in[0];
    const float* rel_embeds = (const float*)d_in[1];
    const float* Wr1  = (const float*)d_in[2];
    const float* Wsl1 = (const float*)d_in[3];
    const float* Wel1 = (const float*)d_in[4];
    const float* Wr2  = (const float*)d_in[5];
    const float* Wsl2 = (const float*)d_in[6];
    const float* Wel2 = (const float*)d_in[7];
    const float* lin_W = (const float*)d_in[8];
    const float* lin_b = (const float*)d_in[9];
    const float* gru_Wih = (const float*)d_in[10];
    const float* gru_Whh = (const float*)d_in[11];
    const float* gru_bih = (const float*)d_in[12];
    const float* gru_bhh = (const float*)d_in[13];
    const float* conve_w = (const float*)d_in[14];
    const float* conve_b = (const float*)d_in[15];
    const float* fce_w = (const float*)d_in[16];
    const float* fce_b = (const float*)d_in[17];
    const float* convr_w = (const float*)d_in[18];
    const float* convr_b = (const float*)d_in[19];
    const float* fcr_w = (const float*)d_in[20];
    const float* fcr_b = (const float*)d_in[21];
    const int* src  = (const int*)d_in[22];
    const int* dst  = (const int*)d_in[23];
    const int* erel = (const int*)d_in[24];
    const int* subj = (const int*)d_in[25];
    const int* relI = (const int*)d_in[26];
    const int* objI = (const int*)d_in[27];
    float* out = (float*)d_out;

    float* p_entA  = (float*)symaddr(g_ent);
    float* p_entB  = (float*)symaddr(g_entB);
    float* p_h1    = (float*)symaddr(g_h1);
    float* p_h2    = (float*)symaddr(g_h2);
    float* p_pre   = (float*)symaddr(g_pre);
    float* p_S     = (float*)symaddr(g_S);
    float* p_winv  = (float*)symaddr(g_winv);
    float* p_rnorm = (float*)symaddr(g_rnorm);
    float* p_relh  = (float*)symaddr(g_relh);
    float* p_x     = (float*)symaddr(g_x);
    float* p_gi    = (float*)symaddr(g_gi);
    float* p_gh    = (float*)symaddr(g_gh);
    float* p_feat  = (float*)symaddr(g_feat);
    float* p_dec   = (float*)symaddr(g_dec);
    float* p_part  = (float*)symaddr(g_part);

    normalize_rows<<<Nn, 256>>>(ent_embeds, p_entA, Nn);
    normalize_rows<<<Rr, 256>>>(rel_embeds, p_relh, Rr);

    const float* Wr_[2]  = {Wr1, Wr2};
    const float* Wsl_[2] = {Wsl1, Wsl2};
    const float* Wel_[2] = {Wel1, Wel2};

    #define TGX(Nc) (((Nc)+127)/128)
    #define TGY(Mr) (((Mr)+127)/128)

    float* entIn = p_entA;
    float* entOut = p_entB;

    for (int t = 0; t < Tt; t++) {
        const int* srcT  = src  + t*Ee;
        const int* dstT  = dst  + t*Ee;
        const int* erelT = erel + t*Ee;

        zero_prep<<<(Nn + 255)/256, 256>>>();
        hist_kernel<<<160, 256>>>(erelT, dstT);
        scan_rel_k<<<1, 512>>>();
        scan_node_a<<<NBLK, 256>>>();
        scan_node_b<<<1, 128>>>();
        scan_node_c<<<NBLK, 256>>>();
        scatter_edges<<<(Ee + 255)/256, 256>>>(erelT, dstT);
        build_misc<<<(Nn + 255)/256, 256>>>();

        // relation-level GRU
        rel_mean<<<Rr, 256>>>(srcT, entIn);
        build_x<<<(Rr*2*Hh + 255)/256, 256>>>(rel_embeds);
        tgemm<4,1><<<dim3(TGX(3*Hh), TGY(Rr)), 256>>>(p_x, gru_Wih, p_gi, Rr, 3*Hh, 2*Hh, 0, gru_bih, nullptr, nullptr);
        tgemm<4,1><<<dim3(TGX(3*Hh), TGY(Rr)), 256>>>(p_relh, gru_Whh, p_gh, Rr, 3*Hh, Hh, 0, gru_bhh, nullptr, nullptr);
        gru_gate<<<Rr, 256>>>();

        // two RGCN layers (scatter-then-GEMM factorization)
        for (int l = 0; l < 2; l++) {
            const float* hin = (l == 0) ? entIn : p_h1;
            float* hout = (l == 0) ? p_h1 : p_h2;
            gather_pre<<<Nn, 256>>>(srcT, erelT, hin);
            tgemm<0,1><<<dim3(TGX(Hh), TGY(Nn)), 256>>>(hin, Wsl_[l], p_S, Nn, Hh, Hh, 0, nullptr, nullptr, nullptr);
            tgemm<1,1><<<dim3(TGX(Hh), TGY(Nn)), 256>>>(p_pre, Wr_[l], hout, Nn, Hh, Hh, 0, nullptr, p_S, p_rnorm);
            fixup_zero<<<64, 256>>>(Wel_[l], hin, hout);
        }

        // entity update: fused sigmoid-gate GEMM writes entOut
        rownorm_inv<<<(Nn + 7)/8, 256>>>();
        tgemm<5,1><<<dim3(TGX(Hh), TGY(Nn)), 256>>>(entIn, lin_W, entOut, Nn, Hh, Hh, 0, lin_b, p_h2, p_winv);
        copy_relh<<<(Rr*Hh + 255)/256, 256>>>();

        float* tmp = entIn; entIn = entOut; entOut = tmp;
    }
    // after swap, entIn points at the final entity embeddings
    float* entF = entIn;

    const int klen = CH / KSPLIT;   // 1000

    // ---- decoder: obj logits ----
    dec_gather<<<(Bb*Hh + 255)/256, 256>>>(subj, relI, entF, 0);
    conv_feat<<<Bb, 256>>>(conve_w, conve_b);
    tgemm<0,KSPLIT><<<dim3(TGX(Hh), TGY(Bb), KSPLIT), 256>>>(p_feat, fce_w, p_part, Bb, Hh, CH, klen, nullptr, nullptr, nullptr);
    split_reduce_relu<<<(Bb*Hh + 255)/256, 256>>>(p_dec, fce_b);
    tgemm<0,1><<<dim3(TGX(Nn), TGY(Bb)), 256>>>(p_dec, entF, out, Bb, Nn, Hh, 0, nullptr, nullptr, nullptr);

    // ---- decoder: rel logits ----
    dec_gather<<<(Bb*Hh + 255)/256, 256>>>(subj, objI, entF, 1);
    conv_feat<<<Bb, 256>>>(convr_w, convr_b);
    tgemm<0,KSPLIT><<<dim3(TGX(Hh), TGY(Bb), KSPLIT), 256>>>(p_feat, fcr_w, p_part, Bb, Hh, CH, klen, nullptr, nullptr, nullptr);
    split_reduce_relu<<<(Bb*Hh + 255)/256, 256>>>(p_dec, fcr_b);
    tgemm<0,1><<<dim3(TGX(Rr), TGY(Bb)), 256>>>(p_dec, p_relh, out + (size_t)Bb*Nn, Bb, Rr, Hh, 0, nullptr, nullptr, nullptr);
}